// round 3
// baseline (speedup 1.0000x reference)
#include <cuda_runtime.h>
#include <math.h>

// ---------------------------------------------------------------------------
// NNConvNet fused GNN forward — R1: lane=k edge kernel + f32x2.
// Phase 1 (lane=edge): ef -> h1 -> h2, stage h2/x_src/dst in smem.
// Phase 2 (lane=k):    fused w=relu(h2@W3+b3) and msg = sum_h x_h*w[h,k],
//                      4 edges register-blocked, fma.rn.f32x2 along j,
//                      W3 read coalesced (each lane its own k column).
// ---------------------------------------------------------------------------

#define NMAX 20000
#define EMAX 320000
#define BATCH 64

typedef unsigned long long ull;

__device__ float g_x[NMAX * 32];
__device__ float g_agg[NMAX * 32];
__device__ float g_pooled[BATCH * 32];
__device__ float g_counts[BATCH];
__device__ unsigned int g_ticket[3];

__constant__ int c_IDX[36] = {
    0, 1, 2,  3,  4,  5,
    1, 6, 7,  8,  9,  10,
    2, 7, 11, 12, 13, 14,
    3, 8, 12, 15, 16, 17,
    4, 9, 13, 16, 18, 19,
    5, 10,14, 17, 19, 20};

// ---------------------------------------------------------------------------
__global__ void init_kernel(const float* __restrict__ node_attrs,
                            const float* __restrict__ embW,
                            const float* __restrict__ embB, int N) {
    int idx = blockIdx.x * blockDim.x + threadIdx.x;
    if (idx < N * 32) {
        int k = idx & 31;
        g_x[idx] = fmaf(node_attrs[idx >> 5], embW[k], embB[k]);
        g_agg[idx] = 0.f;
    }
    if (idx < BATCH * 32) g_pooled[idx] = 0.f;
    if (idx < BATCH) g_counts[idx] = 0.f;
    if (idx < 3) g_ticket[idx] = 0u;
}

// ---------------------------------------------------------------------------
// Edge kernel, 256 threads (8 warps), 1 CTA/SM, persistent + ticket.
// ---------------------------------------------------------------------------
#define EK_THREADS 256
#define EK_WARPS 8

// smem layout (floats)
#define SO_W3 0                 // 32768: W3[j][col] natural layout
#define SO_B3 32768             // 1024
#define SO_W1 33792             // 160
#define SO_B1 33952             // 32
#define SO_W2T 33984            // 1024: W2T[k*32+j]
#define SO_B2 35008             // 32
#define SO_WS 35040             // per-warp: h2s(32*34) + xs(32*33) + dst(32)
#define WS_SIZE 2208
#define SMEM_FLOATS (SO_WS + EK_WARPS * WS_SIZE)

__device__ __forceinline__ ull pack2(float lo, float hi) {
    ull r;
    asm("mov.b64 %0, {%1, %2};" : "=l"(r) : "f"(lo), "f"(hi));
    return r;
}
__device__ __forceinline__ void unpack2(ull v, float& lo, float& hi) {
    asm("mov.b64 {%0, %1}, %2;" : "=f"(lo), "=f"(hi) : "l"(v));
}
__device__ __forceinline__ void fma2(ull& d, ull a, ull b) {
    asm("fma.rn.f32x2 %0, %1, %2, %0;" : "+l"(d) : "l"(a), "l"(b));
}
__device__ __forceinline__ void add2(ull& d, ull a, ull b) {
    asm("add.rn.f32x2 %0, %1, %2;" : "=l"(d) : "l"(a), "l"(b));
}

__global__ void __launch_bounds__(EK_THREADS, 1)
edge_kernel(const float* __restrict__ positions,
            const float* __restrict__ shifts,
            const float* __restrict__ edge_attr,
            const int* __restrict__ eidx,
            const float* __restrict__ W1, const float* __restrict__ b1,
            const float* __restrict__ W2, const float* __restrict__ b2,
            const float* __restrict__ W3, const float* __restrict__ b3,
            int E, int layer) {
    extern __shared__ float sm[];

    // Stage weights (W3 in NATURAL layout: row j, 1024 cols -> coalesced
    // lane=k reads later).
    for (int i = threadIdx.x; i < 32 * 1024; i += EK_THREADS)
        sm[SO_W3 + i] = W3[i];
    for (int i = threadIdx.x; i < 1024; i += EK_THREADS) {
        sm[SO_B3 + i] = b3[i];
        int j = i >> 5, k = i & 31;
        sm[SO_W2T + k * 32 + j] = W2[i];
    }
    if (threadIdx.x < 160) sm[SO_W1 + threadIdx.x] = W1[threadIdx.x];
    if (threadIdx.x < 32) {
        sm[SO_B1 + threadIdx.x] = b1[threadIdx.x];
        sm[SO_B2 + threadIdx.x] = b2[threadIdx.x];
    }
    __syncthreads();

    const int lane = threadIdx.x & 31;
    const int warp = threadIdx.x >> 5;
    float* h2s = sm + SO_WS + warp * WS_SIZE;   // [32][34]
    float* xs = h2s + 32 * 34;                  // [32][33]
    int* dsts = (int*)(xs + 32 * 33);           // [32]

    const int* srcp = eidx;
    const int* dstp = eidx + E;
    const int ntasks = (E + 31) >> 5;

    for (;;) {
        int task;
        if (lane == 0) task = (int)atomicAdd(&g_ticket[layer], 1u);
        task = __shfl_sync(0xffffffffu, task, 0);
        if (task >= ntasks) break;

        // ---------------- Phase 1: lane = edge ----------------
        int e = task * 32 + lane;
        bool valid = e < E;
        float vx = 0.f, vy = 0.f, vz = 0.f, ea = 0.f;
        int si = 0, di = 0;
        if (valid) {
            si = srcp[e];
            di = dstp[e];
            float px = positions[si * 3 + 0], py = positions[si * 3 + 1],
                  pz = positions[si * 3 + 2];
            float qx = positions[di * 3 + 0], qy = positions[di * 3 + 1],
                  qz = positions[di * 3 + 2];
            vx = qx - px + shifts[e * 3 + 0];
            vy = qy - py + shifts[e * 3 + 1];
            vz = qz - pz + shifts[e * 3 + 2];
            ea = edge_attr[e];
        }
        dsts[lane] = valid ? di : 0;
        float len = sqrtf(vx * vx + vy * vy + vz * vz);

        // h1
        float h1[32];
#pragma unroll
        for (int k = 0; k < 32; k++) {
            float a = sm[SO_B1 + k];
            a = fmaf(vx, sm[SO_W1 + 0 * 32 + k], a);
            a = fmaf(vy, sm[SO_W1 + 1 * 32 + k], a);
            a = fmaf(vz, sm[SO_W1 + 2 * 32 + k], a);
            a = fmaf(len, sm[SO_W1 + 3 * 32 + k], a);
            a = fmaf(ea, sm[SO_W1 + 4 * 32 + k], a);
            h1[k] = fmaxf(a, 0.f);
        }

        // h2 -> smem (zero for invalid edges so phase-2 msg contributions = 0)
#pragma unroll
        for (int k = 0; k < 32; k++) {
            const float4* wp = (const float4*)&sm[SO_W2T + k * 32];
            float a0 = sm[SO_B2 + k], a1 = 0.f, a2 = 0.f, a3 = 0.f;
#pragma unroll
            for (int j = 0; j < 8; j++) {
                float4 w = wp[j];
                a0 = fmaf(h1[4 * j + 0], w.x, a0);
                a1 = fmaf(h1[4 * j + 1], w.y, a1);
                a2 = fmaf(h1[4 * j + 2], w.z, a2);
                a3 = fmaf(h1[4 * j + 3], w.w, a3);
            }
            h2s[lane * 34 + k] = valid ? fmaxf((a0 + a1) + (a2 + a3), 0.f) : 0.f;
        }

        // x[src] -> smem (zero if invalid -> msg stays 0)
        if (valid) {
            const float4* xr = (const float4*)(g_x + (size_t)si * 32);
#pragma unroll
            for (int t = 0; t < 8; t++) {
                float4 v = xr[t];
                xs[lane * 33 + 4 * t + 0] = v.x;
                xs[lane * 33 + 4 * t + 1] = v.y;
                xs[lane * 33 + 4 * t + 2] = v.z;
                xs[lane * 33 + 4 * t + 3] = v.w;
            }
        } else {
#pragma unroll
            for (int t = 0; t < 32; t++) xs[lane * 33 + t] = 0.f;
        }
        __syncwarp();

        // ---------------- Phase 2: lane = k, 4 edges per pass ----------------
#pragma unroll 1
        for (int g = 0; g < 8; g++) {
            const int e0 = g * 4;
            // h2 pairs into registers (LDS.64 broadcast), 4 edges x 16 pairs
            ull h2p0[16], h2p1[16], h2p2[16], h2p3[16];
#pragma unroll
            for (int t = 0; t < 16; t++) {
                h2p0[t] = *(const ull*)(h2s + (e0 + 0) * 34 + 2 * t);
                h2p1[t] = *(const ull*)(h2s + (e0 + 1) * 34 + 2 * t);
                h2p2[t] = *(const ull*)(h2s + (e0 + 2) * 34 + 2 * t);
                h2p3[t] = *(const ull*)(h2s + (e0 + 3) * 34 + 2 * t);
            }
            float msg0 = 0.f, msg1 = 0.f, msg2 = 0.f, msg3 = 0.f;

#pragma unroll 1
            for (int h = 0; h < 32; h++) {
                float b3k = sm[SO_B3 + (h << 5) + lane];   // coalesced
                ull bpair = pack2(b3k, 0.f);

                // weights: coalesced LDS.32, lane owns column h*32+lane
                float w[32];
#pragma unroll
                for (int j = 0; j < 32; j++)
                    w[j] = sm[SO_W3 + (j << 10) + (h << 5) + lane];
                ull wp[16];
#pragma unroll
                for (int t = 0; t < 16; t++) wp[t] = pack2(w[2 * t], w[2 * t + 1]);

                float xh0 = xs[(e0 + 0) * 33 + h];
                float xh1 = xs[(e0 + 1) * 33 + h];
                float xh2 = xs[(e0 + 2) * 33 + h];
                float xh3 = xs[(e0 + 3) * 33 + h];

#define EDGE_BODY(HP, XH, MSG)                                        \
                {                                                     \
                    ull accA = bpair, accB = 0ull;                    \
                    _Pragma("unroll")                                 \
                    for (int t = 0; t < 8; t++) fma2(accA, HP[t], wp[t]); \
                    _Pragma("unroll")                                 \
                    for (int t = 8; t < 16; t++) fma2(accB, HP[t], wp[t]); \
                    ull accC; add2(accC, accA, accB);                 \
                    float lo, hi; unpack2(accC, lo, hi);              \
                    float s = fmaxf(lo + hi, 0.f);                    \
                    MSG = fmaf(XH, s, MSG);                           \
                }
                EDGE_BODY(h2p0, xh0, msg0)
                EDGE_BODY(h2p1, xh1, msg1)
                EDGE_BODY(h2p2, xh2, msg2)
                EDGE_BODY(h2p3, xh3, msg3)
#undef EDGE_BODY
            }

            // coalesced atomics: 32 lanes -> one node row
            atomicAdd(&g_agg[(size_t)dsts[e0 + 0] * 32 + lane], msg0);
            atomicAdd(&g_agg[(size_t)dsts[e0 + 1] * 32 + lane], msg1);
            atomicAdd(&g_agg[(size_t)dsts[e0 + 2] * 32 + lane], msg2);
            atomicAdd(&g_agg[(size_t)dsts[e0 + 3] * 32 + lane], msg3);
        }
        __syncwarp();
    }
}

// ---------------------------------------------------------------------------
__global__ void node_kernel(const float* __restrict__ conv_b, int N) {
    int idx = blockIdx.x * blockDim.x + threadIdx.x;
    if (idx < N * 32) {
        float v = g_agg[idx] + conv_b[idx & 31];
        g_x[idx] += fmaxf(v, 0.f);
        g_agg[idx] = 0.f;
    }
}

__global__ void pool_kernel(const int* __restrict__ batch_ids, int N) {
    int idx = blockIdx.x * blockDim.x + threadIdx.x;
    if (idx < N * 32) {
        int n = idx >> 5, k = idx & 31;
        int b = batch_ids[n];
        atomicAdd(&g_pooled[b * 32 + k], g_x[idx]);
        if (k == 0) atomicAdd(&g_counts[b], 1.f);
    }
}

__device__ __forceinline__ float selu_f(float x) {
    const float alpha = 1.6732632423543772f;
    const float scale = 1.0507009873554805f;
    return x > 0.f ? scale * x : scale * alpha * expm1f(x);
}

__global__ void mlp_kernel(const float* __restrict__ W1,
                           const float* __restrict__ b1,
                           const float* __restrict__ W2,
                           const float* __restrict__ b2,
                           const float* __restrict__ W3,
                           const float* __restrict__ b3,
                           const float* __restrict__ W4,
                           const float* __restrict__ b4,
                           float* __restrict__ out) {
    __shared__ float sbuf[32][280];
    int warp = threadIdx.x >> 5, lane = threadIdx.x & 31;
    int b = blockIdx.x * 32 + warp;
    if (b >= BATCH) return;
    float* buf = sbuf[warp];

    float cnt = fmaxf(g_counts[b], 1.f);
    buf[lane] = g_pooled[b * 32 + lane] / cnt;
    __syncwarp();

#pragma unroll
    for (int r = 0; r < 4; r++) {
        int o = lane + 32 * r;
        float a = b1[o];
        for (int k = 0; k < 32; k++) a = fmaf(buf[k], W1[k * 128 + o], a);
        buf[32 + o] = selu_f(a);
    }
    __syncwarp();
#pragma unroll
    for (int r = 0; r < 2; r++) {
        int o = lane + 32 * r;
        float a = b2[o];
        for (int k = 0; k < 128; k++) a = fmaf(buf[32 + k], W2[k * 64 + o], a);
        buf[160 + o] = selu_f(a);
    }
    __syncwarp();
    {
        int o = lane;
        float a = b3[o];
        for (int k = 0; k < 64; k++) a = fmaf(buf[160 + k], W3[k * 32 + o], a);
        buf[224 + o] = selu_f(a);
    }
    __syncwarp();
    if (lane < 21) {
        float a = b4[lane];
        for (int k = 0; k < 32; k++) a = fmaf(buf[224 + k], W4[k * 21 + lane], a);
        buf[256 + lane] = a;
    }
    __syncwarp();
    for (int r = lane; r < 36; r += 32) out[b * 36 + r] = buf[256 + c_IDX[r]];
}

// ---------------------------------------------------------------------------
extern "C" void kernel_launch(void* const* d_in, const int* in_sizes, int n_in,
                              void* d_out, int out_size) {
    const float* node_attrs = (const float*)d_in[0];
    const float* positions = (const float*)d_in[1];
    const float* shifts = (const float*)d_in[2];
    const float* edge_attr = (const float*)d_in[3];
    const int* edge_index = (const int*)d_in[4];
    const int* batch_ids = (const int*)d_in[5];
    const float* embed_W = (const float*)d_in[6];
    const float* embed_b = (const float*)d_in[7];
    const float* e_W1 = (const float*)d_in[8];
    const float* e_b1 = (const float*)d_in[9];
    const float* e_W2 = (const float*)d_in[10];
    const float* e_b2 = (const float*)d_in[11];
    const float* e_W3 = (const float*)d_in[12];
    const float* e_b3 = (const float*)d_in[13];
    const float* conv_b = (const float*)d_in[14];
    const float* h_W1 = (const float*)d_in[15];
    const float* h_b1 = (const float*)d_in[16];
    const float* h_W2 = (const float*)d_in[17];
    const float* h_b2 = (const float*)d_in[18];
    const float* h_W3 = (const float*)d_in[19];
    const float* h_b3 = (const float*)d_in[20];
    const float* h_W4 = (const float*)d_in[21];
    const float* h_b4 = (const float*)d_in[22];

    int N = in_sizes[0];
    int E = in_sizes[3];
    if (N > NMAX) N = NMAX;
    if (E > EMAX) E = EMAX;

    size_t smem_bytes = (size_t)SMEM_FLOATS * sizeof(float);
    cudaFuncSetAttribute(edge_kernel,
                         cudaFuncAttributeMaxDynamicSharedMemorySize,
                         (int)smem_bytes);

    int tot = N * 32;
    int blk = 256;
    init_kernel<<<(tot + blk - 1) / blk, blk>>>(node_attrs, embed_W, embed_b, N);

    for (int l = 0; l < 3; l++) {
        edge_kernel<<<148, EK_THREADS, smem_bytes>>>(
            positions, shifts, edge_attr, edge_index, e_W1 + l * 160,
            e_b1 + l * 32, e_W2 + l * 1024, e_b2 + l * 32, e_W3 + l * 32768,
            e_b3 + l * 1024, E, l);
        node_kernel<<<(tot + blk - 1) / blk, blk>>>(conv_b + l * 32, N);
    }

    pool_kernel<<<(tot + blk - 1) / blk, blk>>>(batch_ids, N);
    mlp_kernel<<<2, 1024>>>(h_W1, h_b1, h_W2, h_b2, h_W3, h_b3, h_W4, h_b4,
                            (float*)d_out);
}

// round 5
// speedup vs baseline: 2.8045x; 2.8045x over previous
#include <cuda_runtime.h>
#include <math.h>

// ---------------------------------------------------------------------------
// NNConvNet fused GNN — R4: legacy mma.sync (HMMA) bf16 2-split W3 GEMM.
// tcgen05 is unavailable (harness targets sm_103 without the 'a' feature set),
// so the tensor path uses standard PTX mma.sync.m16n8k16.bf16 + ldmatrix.
//
// Per warp-tile (32 edges, warp-autonomous, no CTA sync in loop):
//  phase1: thread=edge: ef->h1->h2 (fp32), split h2 -> bf16 [Ah|Al] row in
//          smem (144B stride, conflict-free ldmatrix); x[src] -> xs; dst.
//  GEMM:   D[32x1024] = h2 @ W3, 16 chunks of n=64:
//          acc init = b3 (LDS.64), 96 mma/chunk (AhBh + AlBh + AhBl, k16x2),
//          B via ldmatrix.x4.trans from [k][n] smem (2064B stride).
//  epi:    msg[row,k] += x[row,h] * relu(acc); packed fma.rn.f32x2,
//          msg in 16 f32x2 regs (4 rows x 4 k-pairs per lane).
//  scatter: 32 atomicAdd per lane to g_agg[dst].
// ---------------------------------------------------------------------------

#define NMAX 20000
#define EMAX 320000
#define BATCH 64

typedef unsigned int u32;
typedef unsigned long long u64;
typedef unsigned short u16;
typedef unsigned long long ull;

__device__ float g_x[NMAX * 32];
__device__ float g_agg[NMAX * 32];
__device__ float g_pooled[BATCH * 32];
__device__ float g_counts[BATCH];

__constant__ int c_IDX[36] = {
    0, 1, 2,  3,  4,  5,
    1, 6, 7,  8,  9,  10,
    2, 7, 11, 12, 13, 14,
    3, 8, 12, 15, 16, 17,
    4, 9, 13, 16, 18, 19,
    5, 10,14, 17, 19, 20};

// ---------------- smem layout ----------------
// floats:
#define F_W1 0        // 160
#define F_B1 160      // 32
#define F_B2 192      // 32
#define F_W2T 224     // 1024
#define F_B3S 1248    // 1024
// bytes:
#define OFF_DSTS 9088            // 8 warps * 32 int
#define OFF_XS 10112             // 8 warps * 32*33 fp32 = 33792
#define OFF_A 43904              // 8 warps * 32 rows * 144B = 36864
#define OFF_B 80768              // 64 rows * 2064B = 132096
#define A_STRIDE 144
#define B_STRIDE 2064
#define SMEM_TOTAL 212864

// ---------------- PTX helpers ----------------
__device__ __forceinline__ u32 smem_u32(const void* p) {
    u32 a;
    asm("{ .reg .u64 t; cvta.to.shared.u64 t, %1; cvt.u32.u64 %0, t; }"
        : "=r"(a) : "l"(p));
    return a;
}
__device__ __forceinline__ void ldsm_x4(u32* r, u32 addr) {
    asm volatile(
        "ldmatrix.sync.aligned.m8n8.x4.shared.b16 {%0,%1,%2,%3}, [%4];"
        : "=r"(r[0]), "=r"(r[1]), "=r"(r[2]), "=r"(r[3]) : "r"(addr));
}
__device__ __forceinline__ void ldsm_x4t(u32* r, u32 addr) {
    asm volatile(
        "ldmatrix.sync.aligned.m8n8.x4.trans.shared.b16 {%0,%1,%2,%3}, [%4];"
        : "=r"(r[0]), "=r"(r[1]), "=r"(r[2]), "=r"(r[3]) : "r"(addr));
}
__device__ __forceinline__ void mma_bf16(float* d, const u32* a, u32 b0,
                                         u32 b1) {
    asm volatile(
        "mma.sync.aligned.m16n8k16.row.col.f32.bf16.bf16.f32 "
        "{%0,%1,%2,%3}, {%4,%5,%6,%7}, {%8,%9}, {%0,%1,%2,%3};"
        : "+f"(d[0]), "+f"(d[1]), "+f"(d[2]), "+f"(d[3])
        : "r"(a[0]), "r"(a[1]), "r"(a[2]), "r"(a[3]), "r"(b0), "r"(b1));
}
__device__ __forceinline__ ull pack2(float lo, float hi) {
    ull r;
    asm("mov.b64 %0, {%1, %2};" : "=l"(r) : "f"(lo), "f"(hi));
    return r;
}
__device__ __forceinline__ void unpack2(ull v, float& lo, float& hi) {
    asm("mov.b64 {%0, %1}, %2;" : "=f"(lo), "=f"(hi) : "l"(v));
}
__device__ __forceinline__ void fma2(ull& d, ull a, ull b) {
    asm("fma.rn.f32x2 %0, %1, %2, %0;" : "+l"(d) : "l"(a), "l"(b));
}
__device__ __forceinline__ u32 bf2_bits(float lo, float hi) {
    u32 r;
    asm("cvt.rn.bf16x2.f32 %0, %1, %2;" : "=r"(r) : "f"(hi), "f"(lo));
    return r;
}
__device__ __forceinline__ u16 bf1_bits(float v) {
    u16 r;
    asm("{.reg .b16 t; cvt.rn.bf16.f32 t, %1; mov.b16 %0, t;}"
        : "=h"(r) : "f"(v));
    return r;
}

// ---------------------------------------------------------------------------
__global__ void init_kernel(const float* __restrict__ node_attrs,
                            const float* __restrict__ embW,
                            const float* __restrict__ embB, int N) {
    int idx = blockIdx.x * blockDim.x + threadIdx.x;
    if (idx < N * 32) {
        int k = idx & 31;
        g_x[idx] = fmaf(node_attrs[idx >> 5], embW[k], embB[k]);
        g_agg[idx] = 0.f;
    }
    if (idx < BATCH * 32) g_pooled[idx] = 0.f;
    if (idx < BATCH) g_counts[idx] = 0.f;
}

// ---------------------------------------------------------------------------
__global__ void __launch_bounds__(256, 1)
edge_kernel(const float* __restrict__ positions,
            const float* __restrict__ shifts,
            const float* __restrict__ edge_attr,
            const int* __restrict__ eidx,
            const float* __restrict__ W1, const float* __restrict__ b1,
            const float* __restrict__ W2, const float* __restrict__ b2,
            const float* __restrict__ W3, const float* __restrict__ b3,
            int E) {
    extern __shared__ float smf[];
    char* smc = (char*)smf;
    const u32 sb = smem_u32(smf);
    const int tid = threadIdx.x;
    const int lane = tid & 31;
    const int warp = tid >> 5;

    // ---- stage B = bf16 split of W3: rows 0..31 = Bh[k][n], 32..63 = Bl ----
    for (int i = tid; i < 32768; i += 256) {
        int j = i >> 10, col = i & 1023;
        float w = W3[i];
        u16 hb = bf1_bits(w);
        float fh = __uint_as_float(((u32)hb) << 16);
        u16 lb = bf1_bits(w - fh);
        *(u16*)(smc + OFF_B + j * B_STRIDE + col * 2) = hb;
        *(u16*)(smc + OFF_B + (j + 32) * B_STRIDE + col * 2) = lb;
    }
    for (int i = tid; i < 1024; i += 256) {
        smf[F_B3S + i] = b3[i];
        int j = i >> 5, k = i & 31;
        smf[F_W2T + k * 32 + j] = W2[i];
    }
    if (tid < 160) smf[F_W1 + tid] = W1[tid];
    if (tid < 32) {
        smf[F_B1 + tid] = b1[tid];
        smf[F_B2 + tid] = b2[tid];
    }
    __syncthreads();

    const int g = lane >> 2;     // fragment row group
    const int tq = lane & 3;     // fragment col group
    char* arow_base = smc + OFF_A + (warp * 32) * A_STRIDE;
    const u32 aw = sb + OFF_A + (u32)(warp * 32) * A_STRIDE;
    float* xw = (float*)(smc + OFF_XS) + warp * (32 * 33);
    int* dstw = (int*)(smc + OFF_DSTS) + warp * 32;

    // ldmatrix lane address components (shared by A and B tiles)
    const int rowoff = ((lane >> 3) & 1) * 8 + (lane & 7);
    const int colb16 = (lane >> 4) * 16;   // byte col offset (A, 8 bf16)

    const int* srcp = eidx;
    const int* dstp = eidx + E;
    const int ntiles = (E + 31) >> 5;
    const int gw = blockIdx.x * 8 + warp;
    const int gstride = gridDim.x * 8;

    for (int tile = gw; tile < ntiles; tile += gstride) {
        // ================= phase 1: thread = edge =================
        int e = (tile << 5) + lane;
        bool valid = e < E;
        float vx = 0.f, vy = 0.f, vz = 0.f, ea = 0.f;
        int si = 0, di = -1;
        if (valid) {
            si = srcp[e];
            di = dstp[e];
            float px = positions[si * 3 + 0], py = positions[si * 3 + 1],
                  pz = positions[si * 3 + 2];
            float qx = positions[di * 3 + 0], qy = positions[di * 3 + 1],
                  qz = positions[di * 3 + 2];
            vx = qx - px + shifts[e * 3 + 0];
            vy = qy - py + shifts[e * 3 + 1];
            vz = qz - pz + shifts[e * 3 + 2];
            ea = edge_attr[e];
        }
        dstw[lane] = valid ? di : -1;
        float len = sqrtf(vx * vx + vy * vy + vz * vz);

        float h1[32];
#pragma unroll
        for (int k = 0; k < 32; k++) {
            float a = smf[F_B1 + k];
            a = fmaf(vx, smf[F_W1 + 0 * 32 + k], a);
            a = fmaf(vy, smf[F_W1 + 1 * 32 + k], a);
            a = fmaf(vz, smf[F_W1 + 2 * 32 + k], a);
            a = fmaf(len, smf[F_W1 + 3 * 32 + k], a);
            a = fmaf(ea, smf[F_W1 + 4 * 32 + k], a);
            h1[k] = fmaxf(a, 0.f);
        }
        float h2[32];
#pragma unroll
        for (int k = 0; k < 32; k++) {
            const float4* wp = (const float4*)&smf[F_W2T + k * 32];
            float a0 = smf[F_B2 + k], a1 = 0.f, a2 = 0.f, a3 = 0.f;
#pragma unroll
            for (int j = 0; j < 8; j++) {
                float4 w = wp[j];
                a0 = fmaf(h1[4 * j + 0], w.x, a0);
                a1 = fmaf(h1[4 * j + 1], w.y, a1);
                a2 = fmaf(h1[4 * j + 2], w.z, a2);
                a3 = fmaf(h1[4 * j + 3], w.w, a3);
            }
            h2[k] = fmaxf((a0 + a1) + (a2 + a3), 0.f);
        }

        // A row: [Ah(32 bf16) | Al(32 bf16)] at row `lane`
        {
            char* arow = arow_base + lane * A_STRIDE;
#pragma unroll
            for (int t = 0; t < 16; t++) {
                float v0 = h2[2 * t], v1 = h2[2 * t + 1];
                u32 hb = bf2_bits(v0, v1);
                float f0 = __uint_as_float((hb & 0xFFFFu) << 16);
                float f1 = __uint_as_float(hb & 0xFFFF0000u);
                u32 lb = bf2_bits(v0 - f0, v1 - f1);
                *(u32*)(arow + 4 * t) = hb;
                *(u32*)(arow + 64 + 4 * t) = lb;
            }
        }
        // x[src]
        if (valid) {
            const float4* xr = (const float4*)(g_x + (size_t)si * 32);
            float* xd = xw + lane * 33;
#pragma unroll
            for (int t = 0; t < 8; t++) {
                float4 v = xr[t];
                xd[4 * t + 0] = v.x;
                xd[4 * t + 1] = v.y;
                xd[4 * t + 2] = v.z;
                xd[4 * t + 3] = v.w;
            }
        }
        __syncwarp();

        // ================= A fragments (held all tile) =================
        u32 Ah[2][2][4], Al[2][2][4];   // [mtile][k16][4]
#pragma unroll
        for (int mt = 0; mt < 2; mt++)
#pragma unroll
            for (int kk = 0; kk < 2; kk++) {
                u32 a = aw + (u32)((mt * 16 + rowoff) * A_STRIDE) +
                        (u32)(kk * 32 + colb16);
                ldsm_x4(Ah[mt][kk], a);
                ldsm_x4(Al[mt][kk], a + 64);
            }

        ull msg[2][2][4];
#pragma unroll
        for (int a = 0; a < 2; a++)
#pragma unroll
            for (int bq = 0; bq < 2; bq++)
#pragma unroll
                for (int t = 0; t < 4; t++) msg[a][bq][t] = 0ull;

        // ================= 16 chunks of n=64 =================
#pragma unroll 1
        for (int chunk = 0; chunk < 16; chunk++) {
            const int cb = chunk * 64;
            float acc[2][8][4];
            // init acc = b3 (broadcast LDS.64)
#pragma unroll
            for (int n8 = 0; n8 < 8; n8++) {
                float2 bb = *(const float2*)(smf + F_B3S + cb + n8 * 8 + 2 * tq);
#pragma unroll
                for (int mt = 0; mt < 2; mt++) {
                    acc[mt][n8][0] = bb.x;
                    acc[mt][n8][1] = bb.y;
                    acc[mt][n8][2] = bb.x;
                    acc[mt][n8][3] = bb.y;
                }
            }
            // GEMM
#pragma unroll
            for (int np = 0; np < 4; np++) {
                u32 nb = (u32)((cb + np * 16) * 2) + (u32)((lane >> 4) * 16);
                u32 bcol = sb + OFF_B + nb;
                u32 bh0[4], bh1[4], bl0[4], bl1[4];
                ldsm_x4t(bh0, bcol + (u32)((rowoff + 0) * B_STRIDE));
                ldsm_x4t(bh1, bcol + (u32)((rowoff + 16) * B_STRIDE));
                ldsm_x4t(bl0, bcol + (u32)((rowoff + 32) * B_STRIDE));
                ldsm_x4t(bl1, bcol + (u32)((rowoff + 48) * B_STRIDE));
#pragma unroll
                for (int mt = 0; mt < 2; mt++) {
                    float* aE = acc[mt][np * 2];
                    float* aO = acc[mt][np * 2 + 1];
                    mma_bf16(aE, Ah[mt][0], bh0[0], bh0[1]);
                    mma_bf16(aE, Ah[mt][1], bh1[0], bh1[1]);
                    mma_bf16(aE, Al[mt][0], bh0[0], bh0[1]);
                    mma_bf16(aE, Al[mt][1], bh1[0], bh1[1]);
                    mma_bf16(aE, Ah[mt][0], bl0[0], bl0[1]);
                    mma_bf16(aE, Ah[mt][1], bl1[0], bl1[1]);
                    mma_bf16(aO, Ah[mt][0], bh0[2], bh0[3]);
                    mma_bf16(aO, Ah[mt][1], bh1[2], bh1[3]);
                    mma_bf16(aO, Al[mt][0], bh0[2], bh0[3]);
                    mma_bf16(aO, Al[mt][1], bh1[2], bh1[3]);
                    mma_bf16(aO, Ah[mt][0], bl0[2], bl0[3]);
                    mma_bf16(aO, Ah[mt][1], bl1[2], bl1[3]);
                }
            }
            // epilogue: msg += x_h * relu(acc)   (acc already includes b3)
#pragma unroll
            for (int mt = 0; mt < 2; mt++) {
#pragma unroll
                for (int hh = 0; hh < 2; hh++) {
                    int h = chunk * 2 + hh;
                    float x0 = xw[(mt * 16 + g) * 33 + h];
                    float x1 = xw[(mt * 16 + 8 + g) * 33 + h];
                    ull xp0 = pack2(x0, x0);
                    ull xp1 = pack2(x1, x1);
#pragma unroll
                    for (int t = 0; t < 4; t++) {
                        const float* d = acc[mt][hh * 4 + t];
                        float f0 = fmaxf(d[0], 0.f), f1 = fmaxf(d[1], 0.f);
                        float f2 = fmaxf(d[2], 0.f), f3 = fmaxf(d[3], 0.f);
                        fma2(msg[mt][0][t], pack2(f0, f1), xp0);
                        fma2(msg[mt][1][t], pack2(f2, f3), xp1);
                    }
                }
            }
        }

        // ================= scatter =================
#pragma unroll
        for (int mt = 0; mt < 2; mt++)
#pragma unroll
            for (int hf = 0; hf < 2; hf++) {
                int row = mt * 16 + hf * 8 + g;
                int d = dstw[row];
                if (d >= 0) {
                    float* ap = g_agg + (size_t)d * 32 + 2 * tq;
#pragma unroll
                    for (int t = 0; t < 4; t++) {
                        float m0, m1;
                        unpack2(msg[mt][hf][t], m0, m1);
                        atomicAdd(ap + 8 * t, m0);
                        atomicAdd(ap + 8 * t + 1, m1);
                    }
                }
            }
        __syncwarp();
    }
}

// ---------------------------------------------------------------------------
__global__ void node_kernel(const float* __restrict__ conv_b, int N) {
    int idx = blockIdx.x * blockDim.x + threadIdx.x;
    if (idx < N * 32) {
        float v = g_agg[idx] + conv_b[idx & 31];
        g_x[idx] += fmaxf(v, 0.f);
        g_agg[idx] = 0.f;
    }
}

__global__ void pool_kernel(const int* __restrict__ batch_ids, int N) {
    int idx = blockIdx.x * blockDim.x + threadIdx.x;
    if (idx < N * 32) {
        int n = idx >> 5, k = idx & 31;
        int b = batch_ids[n];
        atomicAdd(&g_pooled[b * 32 + k], g_x[idx]);
        if (k == 0) atomicAdd(&g_counts[b], 1.f);
    }
}

__device__ __forceinline__ float selu_f(float x) {
    const float alpha = 1.6732632423543772f;
    const float scale = 1.0507009873554805f;
    return x > 0.f ? scale * x : scale * alpha * expm1f(x);
}

__global__ void mlp_kernel(const float* __restrict__ W1,
                           const float* __restrict__ b1,
                           const float* __restrict__ W2,
                           const float* __restrict__ b2,
                           const float* __restrict__ W3,
                           const float* __restrict__ b3,
                           const float* __restrict__ W4,
                           const float* __restrict__ b4,
                           float* __restrict__ out) {
    __shared__ float sbuf[32][280];
    int warp = threadIdx.x >> 5, lane = threadIdx.x & 31;
    int b = blockIdx.x * 32 + warp;
    if (b >= BATCH) return;
    float* buf = sbuf[warp];

    float cnt = fmaxf(g_counts[b], 1.f);
    buf[lane] = g_pooled[b * 32 + lane] / cnt;
    __syncwarp();

#pragma unroll
    for (int r = 0; r < 4; r++) {
        int o = lane + 32 * r;
        float a = b1[o];
        for (int k = 0; k < 32; k++) a = fmaf(buf[k], W1[k * 128 + o], a);
        buf[32 + o] = selu_f(a);
    }
    __syncwarp();
#pragma unroll
    for (int r = 0; r < 2; r++) {
        int o = lane + 32 * r;
        float a = b2[o];
        for (int k = 0; k < 128; k++) a = fmaf(buf[32 + k], W2[k * 64 + o], a);
        buf[160 + o] = selu_f(a);
    }
    __syncwarp();
    {
        int o = lane;
        float a = b3[o];
        for (int k = 0; k < 64; k++) a = fmaf(buf[160 + k], W3[k * 32 + o], a);
        buf[224 + o] = selu_f(a);
    }
    __syncwarp();
    if (lane < 21) {
        float a = b4[lane];
        for (int k = 0; k < 32; k++) a = fmaf(buf[224 + k], W4[k * 21 + lane], a);
        buf[256 + lane] = a;
    }
    __syncwarp();
    for (int r = lane; r < 36; r += 32) out[b * 36 + r] = buf[256 + c_IDX[r]];
}

// ---------------------------------------------------------------------------
extern "C" void kernel_launch(void* const* d_in, const int* in_sizes, int n_in,
                              void* d_out, int out_size) {
    const float* node_attrs = (const float*)d_in[0];
    const float* positions = (const float*)d_in[1];
    const float* shifts = (const float*)d_in[2];
    const float* edge_attr = (const float*)d_in[3];
    const int* edge_index = (const int*)d_in[4];
    const int* batch_ids = (const int*)d_in[5];
    const float* embed_W = (const float*)d_in[6];
    const float* embed_b = (const float*)d_in[7];
    const float* e_W1 = (const float*)d_in[8];
    const float* e_b1 = (const float*)d_in[9];
    const float* e_W2 = (const float*)d_in[10];
    const float* e_b2 = (const float*)d_in[11];
    const float* e_W3 = (const float*)d_in[12];
    const float* e_b3 = (const float*)d_in[13];
    const float* conv_b = (const float*)d_in[14];
    const float* h_W1 = (const float*)d_in[15];
    const float* h_b1 = (const float*)d_in[16];
    const float* h_W2 = (const float*)d_in[17];
    const float* h_b2 = (const float*)d_in[18];
    const float* h_W3 = (const float*)d_in[19];
    const float* h_b3 = (const float*)d_in[20];
    const float* h_W4 = (const float*)d_in[21];
    const float* h_b4 = (const float*)d_in[22];

    int N = in_sizes[0];
    int E = in_sizes[3];
    if (N > NMAX) N = NMAX;
    if (E > EMAX) E = EMAX;

    cudaFuncSetAttribute(edge_kernel,
                         cudaFuncAttributeMaxDynamicSharedMemorySize,
                         SMEM_TOTAL);

    int tot = N * 32;
    int blk = 256;
    init_kernel<<<(tot + blk - 1) / blk, blk>>>(node_attrs, embed_W, embed_b, N);

    for (int l = 0; l < 3; l++) {
        edge_kernel<<<148, 256, SMEM_TOTAL>>>(
            positions, shifts, edge_attr, edge_index, e_W1 + l * 160,
            e_b1 + l * 32, e_W2 + l * 1024, e_b2 + l * 32, e_W3 + l * 32768,
            e_b3 + l * 1024, E);
        node_kernel<<<(tot + blk - 1) / blk, blk>>>(conv_b + l * 32, N);
    }

    pool_kernel<<<(tot + blk - 1) / blk, blk>>>(batch_ids, N);
    mlp_kernel<<<2, 1024>>>(h_W1, h_b1, h_W2, h_b2, h_W3, h_b3, h_W4, h_b4,
                            (float*)d_out);
}

// round 6
// speedup vs baseline: 3.5445x; 1.2638x over previous
#include <cuda_runtime.h>
#include <cuda_fp16.h>
#include <math.h>

// ---------------------------------------------------------------------------
// NNConvNet fused GNN — R5: HMMA fp16 2-term split (A=Ah+Al fp16, B=fp16),
// 12 warps/CTA. D = (Ah+Al)@Bh => error = A*(B-Bh) ~ 2^-12 rel on w.
//
// Per warp-tile (32 edges, warp-autonomous):
//  phase1: thread=edge: ef->h1->h2 (fp32), h2 -> fp16 [Ah|Al] row (144B
//          stride); x[src] -> xs; dst -> dstw.
//  GEMM:   D[32x1024] = h2 @ W3, 16 chunks of n=64: acc init = b3 (LDS.64),
//          per np: 2 ldsm.x4.trans (B fp16) + 8 mma m16n8k16.f16,
//          interleaved across 4 accumulator chains.
//  epi:    msg[row,k] += x[row,h]*relu(acc); packed fma.rn.f32x2.
//  scatter: 32 atomicAdd per lane.
// ---------------------------------------------------------------------------

#define NMAX 20000
#define EMAX 320000
#define BATCH 64
#define NWARPS 12
#define NTHREADS (NWARPS * 32)

typedef unsigned int u32;
typedef unsigned short u16;
typedef unsigned long long ull;

__device__ float g_x[NMAX * 32];
__device__ float g_agg[NMAX * 32];
__device__ float g_pooled[BATCH * 32];
__device__ float g_counts[BATCH];

__constant__ int c_IDX[36] = {
    0, 1, 2,  3,  4,  5,
    1, 6, 7,  8,  9,  10,
    2, 7, 11, 12, 13, 14,
    3, 8, 12, 15, 16, 17,
    4, 9, 13, 16, 18, 19,
    5, 10,14, 17, 19, 20};

// ---------------- smem layout ----------------
// floats:
#define F_W1 0        // 160
#define F_B1 160      // 32
#define F_B2 192      // 32
#define F_W2T 224     // 1024
#define F_B3S 1248    // 1024
// bytes:
#define OFF_DSTS 9088                 // 12 warps * 32 int = 1536
#define OFF_XS 10624                  // 12 warps * 32*33 fp32 = 50688
#define OFF_A 61312                   // 12 warps * 32 rows * 144B = 55296
#define OFF_B 116608                  // 32 rows * 2064B = 66048
#define A_STRIDE 144
#define B_STRIDE 2064
#define SMEM_TOTAL 182656

// ---------------- PTX helpers ----------------
__device__ __forceinline__ u32 smem_u32(const void* p) {
    u32 a;
    asm("{ .reg .u64 t; cvta.to.shared.u64 t, %1; cvt.u32.u64 %0, t; }"
        : "=r"(a) : "l"(p));
    return a;
}
__device__ __forceinline__ void ldsm_x4(u32* r, u32 addr) {
    asm volatile(
        "ldmatrix.sync.aligned.m8n8.x4.shared.b16 {%0,%1,%2,%3}, [%4];"
        : "=r"(r[0]), "=r"(r[1]), "=r"(r[2]), "=r"(r[3]) : "r"(addr));
}
__device__ __forceinline__ void ldsm_x4t(u32* r, u32 addr) {
    asm volatile(
        "ldmatrix.sync.aligned.m8n8.x4.trans.shared.b16 {%0,%1,%2,%3}, [%4];"
        : "=r"(r[0]), "=r"(r[1]), "=r"(r[2]), "=r"(r[3]) : "r"(addr));
}
__device__ __forceinline__ void mma_f16(float* d, const u32* a, u32 b0,
                                        u32 b1) {
    asm volatile(
        "mma.sync.aligned.m16n8k16.row.col.f32.f16.f16.f32 "
        "{%0,%1,%2,%3}, {%4,%5,%6,%7}, {%8,%9}, {%0,%1,%2,%3};"
        : "+f"(d[0]), "+f"(d[1]), "+f"(d[2]), "+f"(d[3])
        : "r"(a[0]), "r"(a[1]), "r"(a[2]), "r"(a[3]), "r"(b0), "r"(b1));
}
__device__ __forceinline__ ull pack2(float lo, float hi) {
    ull r;
    asm("mov.b64 %0, {%1, %2};" : "=l"(r) : "f"(lo), "f"(hi));
    return r;
}
__device__ __forceinline__ void unpack2(ull v, float& lo, float& hi) {
    asm("mov.b64 {%0, %1}, %2;" : "=f"(lo), "=f"(hi) : "l"(v));
}
__device__ __forceinline__ void fma2(ull& d, ull a, ull b) {
    asm("fma.rn.f32x2 %0, %1, %2, %0;" : "+l"(d) : "l"(a), "l"(b));
}
__device__ __forceinline__ u32 h2_bits(__half2 h) {
    u32 r;
    asm("mov.b32 %0, %1;" : "=r"(r) : "r"(*(u32*)&h));
    return *(u32*)&h;
}

// ---------------------------------------------------------------------------
__global__ void init_kernel(const float* __restrict__ node_attrs,
                            const float* __restrict__ embW,
                            const float* __restrict__ embB, int N) {
    int idx = blockIdx.x * blockDim.x + threadIdx.x;
    if (idx < N * 32) {
        int k = idx & 31;
        g_x[idx] = fmaf(node_attrs[idx >> 5], embW[k], embB[k]);
        g_agg[idx] = 0.f;
    }
    if (idx < BATCH * 32) g_pooled[idx] = 0.f;
    if (idx < BATCH) g_counts[idx] = 0.f;
}

// ---------------------------------------------------------------------------
__global__ void __launch_bounds__(NTHREADS, 1)
edge_kernel(const float* __restrict__ positions,
            const float* __restrict__ shifts,
            const float* __restrict__ edge_attr,
            const int* __restrict__ eidx,
            const float* __restrict__ W1, const float* __restrict__ b1,
            const float* __restrict__ W2, const float* __restrict__ b2,
            const float* __restrict__ W3, const float* __restrict__ b3,
            int E) {
    extern __shared__ float smf[];
    char* smc = (char*)smf;
    const u32 sb = smem_u32(smf);
    const int tid = threadIdx.x;
    const int lane = tid & 31;
    const int warp = tid >> 5;

    // ---- stage B = fp16(W3) in [k][n] layout ----
    for (int i = tid; i < 32768; i += NTHREADS) {
        int j = i >> 10, col = i & 1023;
        __half h = __float2half_rn(W3[i]);
        *(u16*)(smc + OFF_B + j * B_STRIDE + col * 2) = *(u16*)&h;
    }
    for (int i = tid; i < 1024; i += NTHREADS) {
        smf[F_B3S + i] = b3[i];
        int j = i >> 5, k = i & 31;
        smf[F_W2T + k * 32 + j] = W2[i];
    }
    if (tid < 160) smf[F_W1 + tid] = W1[tid];
    if (tid < 32) {
        smf[F_B1 + tid] = b1[tid];
        smf[F_B2 + tid] = b2[tid];
    }
    __syncthreads();

    const int g = lane >> 2;     // fragment row group
    const int tq = lane & 3;     // fragment col group
    char* arow_base = smc + OFF_A + (warp * 32) * A_STRIDE;
    const u32 aw = sb + OFF_A + (u32)(warp * 32) * A_STRIDE;
    float* xw = (float*)(smc + OFF_XS) + warp * (32 * 33);
    int* dstw = (int*)(smc + OFF_DSTS) + warp * 32;

    const int rowoff = ((lane >> 3) & 1) * 8 + (lane & 7);
    const int colb16 = (lane >> 4) * 16;

    const int* srcp = eidx;
    const int* dstp = eidx + E;
    const int ntiles = (E + 31) >> 5;
    const int gw = blockIdx.x * NWARPS + warp;
    const int gstride = gridDim.x * NWARPS;

    for (int tile = gw; tile < ntiles; tile += gstride) {
        // ================= phase 1: thread = edge =================
        int e = (tile << 5) + lane;
        bool valid = e < E;
        float vx = 0.f, vy = 0.f, vz = 0.f, ea = 0.f;
        int si = 0, di = -1;
        if (valid) {
            si = srcp[e];
            di = dstp[e];
            float px = positions[si * 3 + 0], py = positions[si * 3 + 1],
                  pz = positions[si * 3 + 2];
            float qx = positions[di * 3 + 0], qy = positions[di * 3 + 1],
                  qz = positions[di * 3 + 2];
            vx = qx - px + shifts[e * 3 + 0];
            vy = qy - py + shifts[e * 3 + 1];
            vz = qz - pz + shifts[e * 3 + 2];
            ea = edge_attr[e];
        }
        dstw[lane] = valid ? di : -1;
        float len = sqrtf(vx * vx + vy * vy + vz * vz);

        float h1[32];
#pragma unroll
        for (int k = 0; k < 32; k++) {
            float a = smf[F_B1 + k];
            a = fmaf(vx, smf[F_W1 + 0 * 32 + k], a);
            a = fmaf(vy, smf[F_W1 + 1 * 32 + k], a);
            a = fmaf(vz, smf[F_W1 + 2 * 32 + k], a);
            a = fmaf(len, smf[F_W1 + 3 * 32 + k], a);
            a = fmaf(ea, smf[F_W1 + 4 * 32 + k], a);
            h1[k] = fmaxf(a, 0.f);
        }
        float h2v[32];
#pragma unroll
        for (int k = 0; k < 32; k++) {
            const float4* wp = (const float4*)&smf[F_W2T + k * 32];
            float a0 = smf[F_B2 + k], a1 = 0.f, a2 = 0.f, a3 = 0.f;
#pragma unroll
            for (int j = 0; j < 8; j++) {
                float4 w = wp[j];
                a0 = fmaf(h1[4 * j + 0], w.x, a0);
                a1 = fmaf(h1[4 * j + 1], w.y, a1);
                a2 = fmaf(h1[4 * j + 2], w.z, a2);
                a3 = fmaf(h1[4 * j + 3], w.w, a3);
            }
            h2v[k] = fmaxf((a0 + a1) + (a2 + a3), 0.f);
        }

        // A row: [Ah(32 fp16) | Al(32 fp16)] at row `lane` (fp16 2-split)
        {
            char* arow = arow_base + lane * A_STRIDE;
#pragma unroll
            for (int t = 0; t < 16; t++) {
                float v0 = h2v[2 * t], v1 = h2v[2 * t + 1];
                __half2 hh = __floats2half2_rn(v0, v1);
                float2 fb = __half22float2(hh);
                __half2 ll = __floats2half2_rn(v0 - fb.x, v1 - fb.y);
                *(u32*)(arow + 4 * t) = *(u32*)&hh;
                *(u32*)(arow + 64 + 4 * t) = *(u32*)&ll;
            }
        }
        // x[src]
        if (valid) {
            const float4* xr = (const float4*)(g_x + (size_t)si * 32);
            float* xd = xw + lane * 33;
#pragma unroll
            for (int t = 0; t < 8; t++) {
                float4 v = xr[t];
                xd[4 * t + 0] = v.x;
                xd[4 * t + 1] = v.y;
                xd[4 * t + 2] = v.z;
                xd[4 * t + 3] = v.w;
            }
        }
        __syncwarp();

        // ================= A fragments (held all tile) =================
        u32 Ah[2][2][4], Al[2][2][4];   // [mtile][k16][4]
#pragma unroll
        for (int mt = 0; mt < 2; mt++)
#pragma unroll
            for (int kk = 0; kk < 2; kk++) {
                u32 a = aw + (u32)((mt * 16 + rowoff) * A_STRIDE) +
                        (u32)(kk * 32 + colb16);
                ldsm_x4(Ah[mt][kk], a);
                ldsm_x4(Al[mt][kk], a + 64);
            }

        ull msg[2][2][4];
#pragma unroll
        for (int a = 0; a < 2; a++)
#pragma unroll
            for (int bq = 0; bq < 2; bq++)
#pragma unroll
                for (int t = 0; t < 4; t++) msg[a][bq][t] = 0ull;

        // ================= 16 chunks of n=64 =================
#pragma unroll 1
        for (int chunk = 0; chunk < 16; chunk++) {
            const int cb = chunk * 64;
            float acc[2][8][4];
#pragma unroll
            for (int n8 = 0; n8 < 8; n8++) {
                float2 bb = *(const float2*)(smf + F_B3S + cb + n8 * 8 + 2 * tq);
#pragma unroll
                for (int mt = 0; mt < 2; mt++) {
                    acc[mt][n8][0] = bb.x;
                    acc[mt][n8][1] = bb.y;
                    acc[mt][n8][2] = bb.x;
                    acc[mt][n8][3] = bb.y;
                }
            }
#pragma unroll
            for (int np = 0; np < 4; np++) {
                u32 bcol = sb + OFF_B + (u32)((cb + np * 16) * 2) +
                           (u32)((lane >> 4) * 16);
                u32 bh0[4], bh1[4];
                ldsm_x4t(bh0, bcol + (u32)((rowoff + 0) * B_STRIDE));
                ldsm_x4t(bh1, bcol + (u32)((rowoff + 16) * B_STRIDE));
                // 8 mma interleaved across 4 independent accumulator chains
                float* aE0 = acc[0][np * 2];
                float* aO0 = acc[0][np * 2 + 1];
                float* aE1 = acc[1][np * 2];
                float* aO1 = acc[1][np * 2 + 1];
                mma_f16(aE0, Ah[0][0], bh0[0], bh0[1]);
                mma_f16(aO0, Ah[0][0], bh0[2], bh0[3]);
                mma_f16(aE1, Ah[1][0], bh0[0], bh0[1]);
                mma_f16(aO1, Ah[1][0], bh0[2], bh0[3]);
                mma_f16(aE0, Ah[0][1], bh1[0], bh1[1]);
                mma_f16(aO0, Ah[0][1], bh1[2], bh1[3]);
                mma_f16(aE1, Ah[1][1], bh1[0], bh1[1]);
                mma_f16(aO1, Ah[1][1], bh1[2], bh1[3]);
                mma_f16(aE0, Al[0][0], bh0[0], bh0[1]);
                mma_f16(aO0, Al[0][0], bh0[2], bh0[3]);
                mma_f16(aE1, Al[1][0], bh0[0], bh0[1]);
                mma_f16(aO1, Al[1][0], bh0[2], bh0[3]);
                mma_f16(aE0, Al[0][1], bh1[0], bh1[1]);
                mma_f16(aO0, Al[0][1], bh1[2], bh1[3]);
                mma_f16(aE1, Al[1][1], bh1[0], bh1[1]);
                mma_f16(aO1, Al[1][1], bh1[2], bh1[3]);
            }
            // epilogue: msg += x_h * relu(acc)
#pragma unroll
            for (int mt = 0; mt < 2; mt++) {
#pragma unroll
                for (int hh = 0; hh < 2; hh++) {
                    int h = chunk * 2 + hh;
                    float x0 = xw[(mt * 16 + g) * 33 + h];
                    float x1 = xw[(mt * 16 + 8 + g) * 33 + h];
                    ull xp0 = pack2(x0, x0);
                    ull xp1 = pack2(x1, x1);
#pragma unroll
                    for (int t = 0; t < 4; t++) {
                        const float* d = acc[mt][hh * 4 + t];
                        float f0 = fmaxf(d[0], 0.f), f1 = fmaxf(d[1], 0.f);
                        float f2 = fmaxf(d[2], 0.f), f3 = fmaxf(d[3], 0.f);
                        fma2(msg[mt][0][t], pack2(f0, f1), xp0);
                        fma2(msg[mt][1][t], pack2(f2, f3), xp1);
                    }
                }
            }
        }

        // ================= scatter =================
#pragma unroll
        for (int mt = 0; mt < 2; mt++)
#pragma unroll
            for (int hf = 0; hf < 2; hf++) {
                int row = mt * 16 + hf * 8 + g;
                int d = dstw[row];
                if (d >= 0) {
                    float* ap = g_agg + (size_t)d * 32 + 2 * tq;
#pragma unroll
                    for (int t = 0; t < 4; t++) {
                        float m0, m1;
                        unpack2(msg[mt][hf][t], m0, m1);
                        atomicAdd(ap + 8 * t, m0);
                        atomicAdd(ap + 8 * t + 1, m1);
                    }
                }
            }
        __syncwarp();
    }
}

// ---------------------------------------------------------------------------
__global__ void node_kernel(const float* __restrict__ conv_b, int N) {
    int idx = blockIdx.x * blockDim.x + threadIdx.x;
    if (idx < N * 32) {
        float v = g_agg[idx] + conv_b[idx & 31];
        g_x[idx] += fmaxf(v, 0.f);
        g_agg[idx] = 0.f;
    }
}

__global__ void pool_kernel(const int* __restrict__ batch_ids, int N) {
    int idx = blockIdx.x * blockDim.x + threadIdx.x;
    if (idx < N * 32) {
        int n = idx >> 5, k = idx & 31;
        int b = batch_ids[n];
        atomicAdd(&g_pooled[b * 32 + k], g_x[idx]);
        if (k == 0) atomicAdd(&g_counts[b], 1.f);
    }
}

__device__ __forceinline__ float selu_f(float x) {
    const float alpha = 1.6732632423543772f;
    const float scale = 1.0507009873554805f;
    return x > 0.f ? scale * x : scale * alpha * expm1f(x);
}

__global__ void mlp_kernel(const float* __restrict__ W1,
                           const float* __restrict__ b1,
                           const float* __restrict__ W2,
                           const float* __restrict__ b2,
                           const float* __restrict__ W3,
                           const float* __restrict__ b3,
                           const float* __restrict__ W4,
                           const float* __restrict__ b4,
                           float* __restrict__ out) {
    __shared__ float sbuf[32][280];
    int warp = threadIdx.x >> 5, lane = threadIdx.x & 31;
    int b = blockIdx.x * 32 + warp;
    if (b >= BATCH) return;
    float* buf = sbuf[warp];

    float cnt = fmaxf(g_counts[b], 1.f);
    buf[lane] = g_pooled[b * 32 + lane] / cnt;
    __syncwarp();

#pragma unroll
    for (int r = 0; r < 4; r++) {
        int o = lane + 32 * r;
        float a = b1[o];
        for (int k = 0; k < 32; k++) a = fmaf(buf[k], W1[k * 128 + o], a);
        buf[32 + o] = selu_f(a);
    }
    __syncwarp();
#pragma unroll
    for (int r = 0; r < 2; r++) {
        int o = lane + 32 * r;
        float a = b2[o];
        for (int k = 0; k < 128; k++) a = fmaf(buf[32 + k], W2[k * 64 + o], a);
        buf[160 + o] = selu_f(a);
    }
    __syncwarp();
    {
        int o = lane;
        float a = b3[o];
        for (int k = 0; k < 64; k++) a = fmaf(buf[160 + k], W3[k * 32 + o], a);
        buf[224 + o] = selu_f(a);
    }
    __syncwarp();
    if (lane < 21) {
        float a = b4[lane];
        for (int k = 0; k < 32; k++) a = fmaf(buf[224 + k], W4[k * 21 + lane], a);
        buf[256 + lane] = a;
    }
    __syncwarp();
    for (int r = lane; r < 36; r += 32) out[b * 36 + r] = buf[256 + c_IDX[r]];
}

// ---------------------------------------------------------------------------
extern "C" void kernel_launch(void* const* d_in, const int* in_sizes, int n_in,
                              void* d_out, int out_size) {
    const float* node_attrs = (const float*)d_in[0];
    const float* positions = (const float*)d_in[1];
    const float* shifts = (const float*)d_in[2];
    const float* edge_attr = (const float*)d_in[3];
    const int* edge_index = (const int*)d_in[4];
    const int* batch_ids = (const int*)d_in[5];
    const float* embed_W = (const float*)d_in[6];
    const float* embed_b = (const float*)d_in[7];
    const float* e_W1 = (const float*)d_in[8];
    const float* e_b1 = (const float*)d_in[9];
    const float* e_W2 = (const float*)d_in[10];
    const float* e_b2 = (const float*)d_in[11];
    const float* e_W3 = (const float*)d_in[12];
    const float* e_b3 = (const float*)d_in[13];
    const float* conv_b = (const float*)d_in[14];
    const float* h_W1 = (const float*)d_in[15];
    const float* h_b1 = (const float*)d_in[16];
    const float* h_W2 = (const float*)d_in[17];
    const float* h_b2 = (const float*)d_in[18];
    const float* h_W3 = (const float*)d_in[19];
    const float* h_b3 = (const float*)d_in[20];
    const float* h_W4 = (const float*)d_in[21];
    const float* h_b4 = (const float*)d_in[22];

    int N = in_sizes[0];
    int E = in_sizes[3];
    if (N > NMAX) N = NMAX;
    if (E > EMAX) E = EMAX;

    cudaFuncSetAttribute(edge_kernel,
                         cudaFuncAttributeMaxDynamicSharedMemorySize,
                         SMEM_TOTAL);

    int tot = N * 32;
    int blk = 256;
    init_kernel<<<(tot + blk - 1) / blk, blk>>>(node_attrs, embed_W, embed_b, N);

    for (int l = 0; l < 3; l++) {
        edge_kernel<<<148, NTHREADS, SMEM_TOTAL>>>(
            positions, shifts, edge_attr, edge_index, e_W1 + l * 160,
            e_b1 + l * 32, e_W2 + l * 1024, e_b2 + l * 32, e_W3 + l * 32768,
            e_b3 + l * 1024, E);
        node_kernel<<<(tot + blk - 1) / blk, blk>>>(conv_b + l * 32, N);
    }

    pool_kernel<<<(tot + blk - 1) / blk, blk>>>(batch_ids, N);
    mlp_kernel<<<2, 1024>>>(h_W1, h_b1, h_W2, h_b2, h_W3, h_b3, h_W4, h_b4,
                            (float*)d_out);
}

// round 7
// speedup vs baseline: 3.6666x; 1.0345x over previous
#include <cuda_runtime.h>
#include <cuda_fp16.h>
#include <math.h>

// ---------------------------------------------------------------------------
// NNConvNet fused GNN — R6: both h2 and W3 GEMMs on HMMA; 14 warps/CTA.
//  phase1 (thread=edge): ef -> h1 (fp32, 5xK); h1 -> fp16 2-split A row.
//  h2 GEMM: h2[32x32] = relu(h1 @ W2 + b2) via mma (h1 2-split x W2 2-split,
//           fp32 acc, b2 acc-init); fragments relu'd, fp16 2-split, written
//           back as A rows for the big GEMM.
//  W3 GEMM: D[32x1024] = h2 @ W3 (A 2-split x B fp16), 32 chunks of n=32
//           (chunk == h); acc init = b3; epi msg[k] += x_h*relu(acc) (f32x2).
//  scatter: 32 atomicAdd per lane, coalesced per fragment layout.
// ---------------------------------------------------------------------------

#define NMAX 20000
#define EMAX 320000
#define BATCH 64
#define NWARPS 14
#define NTHREADS (NWARPS * 32)

typedef unsigned int u32;
typedef unsigned short u16;
typedef unsigned long long ull;

__device__ float g_x[NMAX * 32];
__device__ float g_agg[NMAX * 32];
__device__ float g_pooled[BATCH * 32];
__device__ float g_counts[BATCH];

__constant__ int c_IDX[36] = {
    0, 1, 2,  3,  4,  5,
    1, 6, 7,  8,  9,  10,
    2, 7, 11, 12, 13, 14,
    3, 8, 12, 15, 16, 17,
    4, 9, 13, 16, 18, 19,
    5, 10,14, 17, 19, 20};

// ---------------- smem layout ----------------
// floats:
#define F_W1 0        // 160
#define F_B1 160      // 32
#define F_B2 192      // 32
#define F_B3S 224     // 1024 (ends 1248 floats = 4992 B)
// bytes:
#define OFF_W2H 4992                  // 32 rows * 80 B = 2560
#define OFF_W2L 7552                  // 2560
#define OFF_DSTS 10112                // 14*32*4 = 1792
#define OFF_XS 11904                  // 14*32*33*4 = 59136
#define OFF_A 71040                   // 14*32*144 = 64512
#define OFF_B 135552                  // 32*2064 = 66048
#define A_STRIDE 144
#define B_STRIDE 2064
#define W2_STRIDE 80
#define SMEM_TOTAL 201600

// ---------------- PTX helpers ----------------
__device__ __forceinline__ u32 smem_u32(const void* p) {
    u32 a;
    asm("{ .reg .u64 t; cvta.to.shared.u64 t, %1; cvt.u32.u64 %0, t; }"
        : "=r"(a) : "l"(p));
    return a;
}
__device__ __forceinline__ void ldsm_x4(u32* r, u32 addr) {
    asm volatile(
        "ldmatrix.sync.aligned.m8n8.x4.shared.b16 {%0,%1,%2,%3}, [%4];"
        : "=r"(r[0]), "=r"(r[1]), "=r"(r[2]), "=r"(r[3]) : "r"(addr));
}
__device__ __forceinline__ void ldsm_x4t(u32* r, u32 addr) {
    asm volatile(
        "ldmatrix.sync.aligned.m8n8.x4.trans.shared.b16 {%0,%1,%2,%3}, [%4];"
        : "=r"(r[0]), "=r"(r[1]), "=r"(r[2]), "=r"(r[3]) : "r"(addr));
}
__device__ __forceinline__ void mma_f16(float* d, const u32* a, u32 b0,
                                        u32 b1) {
    asm volatile(
        "mma.sync.aligned.m16n8k16.row.col.f32.f16.f16.f32 "
        "{%0,%1,%2,%3}, {%4,%5,%6,%7}, {%8,%9}, {%0,%1,%2,%3};"
        : "+f"(d[0]), "+f"(d[1]), "+f"(d[2]), "+f"(d[3])
        : "r"(a[0]), "r"(a[1]), "r"(a[2]), "r"(a[3]), "r"(b0), "r"(b1));
}
__device__ __forceinline__ ull pack2(float lo, float hi) {
    ull r;
    asm("mov.b64 %0, {%1, %2};" : "=l"(r) : "f"(lo), "f"(hi));
    return r;
}
__device__ __forceinline__ void unpack2(ull v, float& lo, float& hi) {
    asm("mov.b64 {%0, %1}, %2;" : "=f"(lo), "=f"(hi) : "l"(v));
}
__device__ __forceinline__ void fma2(ull& d, ull a, ull b) {
    asm("fma.rn.f32x2 %0, %1, %2, %0;" : "+l"(d) : "l"(a), "l"(b));
}

// ---------------------------------------------------------------------------
__global__ void init_kernel(const float* __restrict__ node_attrs,
                            const float* __restrict__ embW,
                            const float* __restrict__ embB, int N) {
    int idx = blockIdx.x * blockDim.x + threadIdx.x;
    if (idx < N * 32) {
        int k = idx & 31;
        g_x[idx] = fmaf(node_attrs[idx >> 5], embW[k], embB[k]);
        g_agg[idx] = 0.f;
    }
    if (idx < BATCH * 32) g_pooled[idx] = 0.f;
    if (idx < BATCH) g_counts[idx] = 0.f;
}

// ---------------------------------------------------------------------------
__global__ void __launch_bounds__(NTHREADS, 1)
edge_kernel(const float* __restrict__ positions,
            const float* __restrict__ shifts,
            const float* __restrict__ edge_attr,
            const int* __restrict__ eidx,
            const float* __restrict__ W1, const float* __restrict__ b1,
            const float* __restrict__ W2, const float* __restrict__ b2,
            const float* __restrict__ W3, const float* __restrict__ b3,
            int E) {
    extern __shared__ float smf[];
    char* smc = (char*)smf;
    const u32 sb = smem_u32(smf);
    const int tid = threadIdx.x;
    const int lane = tid & 31;
    const int warp = tid >> 5;

    // ---- stage B = fp16(W3) in [j][n] layout ----
    for (int i = tid; i < 32768; i += NTHREADS) {
        int j = i >> 10, col = i & 1023;
        __half h = __float2half_rn(W3[i]);
        *(u16*)(smc + OFF_B + j * B_STRIDE + col * 2) = *(u16*)&h;
    }
    // ---- W2 fp16 2-split [j][n] ----
    for (int i = tid; i < 1024; i += NTHREADS) {
        int j = i >> 5, n = i & 31;
        float w = W2[i];
        __half hh = __float2half_rn(w);
        __half ll = __float2half_rn(w - __half2float(hh));
        *(u16*)(smc + OFF_W2H + j * W2_STRIDE + n * 2) = *(u16*)&hh;
        *(u16*)(smc + OFF_W2L + j * W2_STRIDE + n * 2) = *(u16*)&ll;
        smf[F_B3S + i] = b3[i];
    }
    if (tid < 160) smf[F_W1 + tid] = W1[tid];
    if (tid < 32) {
        smf[F_B1 + tid] = b1[tid];
        smf[F_B2 + tid] = b2[tid];
    }
    __syncthreads();

    const int g = lane >> 2;     // fragment row group
    const int tq = lane & 3;     // fragment col group
    char* arow_base = smc + OFF_A + (warp * 32) * A_STRIDE;
    const u32 aw = sb + OFF_A + (u32)(warp * 32) * A_STRIDE;
    float* xw = (float*)(smc + OFF_XS) + warp * (32 * 33);
    int* dstw = (int*)(smc + OFF_DSTS) + warp * 32;

    const int rowoff = ((lane >> 3) & 1) * 8 + (lane & 7);
    const int colb16 = (lane >> 4) * 16;

    const int* srcp = eidx;
    const int* dstp = eidx + E;
    const int ntiles = (E + 31) >> 5;
    const int gw = blockIdx.x * NWARPS + warp;
    const int gstride = gridDim.x * NWARPS;

    for (int tile = gw; tile < ntiles; tile += gstride) {
        // ================= phase 1: thread = edge, h1 only =================
        int e = (tile << 5) + lane;
        bool valid = e < E;
        float vx = 0.f, vy = 0.f, vz = 0.f, ea = 0.f;
        int si = 0, di = -1;
        if (valid) {
            si = srcp[e];
            di = dstp[e];
            float px = positions[si * 3 + 0], py = positions[si * 3 + 1],
                  pz = positions[si * 3 + 2];
            float qx = positions[di * 3 + 0], qy = positions[di * 3 + 1],
                  qz = positions[di * 3 + 2];
            vx = qx - px + shifts[e * 3 + 0];
            vy = qy - py + shifts[e * 3 + 1];
            vz = qz - pz + shifts[e * 3 + 2];
            ea = edge_attr[e];
        }
        dstw[lane] = valid ? di : -1;
        float len = sqrtf(vx * vx + vy * vy + vz * vz);

        float h1[32];
#pragma unroll
        for (int k = 0; k < 32; k++) {
            float a = smf[F_B1 + k];
            a = fmaf(vx, smf[F_W1 + 0 * 32 + k], a);
            a = fmaf(vy, smf[F_W1 + 1 * 32 + k], a);
            a = fmaf(vz, smf[F_W1 + 2 * 32 + k], a);
            a = fmaf(len, smf[F_W1 + 3 * 32 + k], a);
            a = fmaf(ea, smf[F_W1 + 4 * 32 + k], a);
            h1[k] = fmaxf(a, 0.f);
        }

        // h1 -> fp16 2-split A row [h1h(32)|h1l(32)]
        {
            char* arow = arow_base + lane * A_STRIDE;
#pragma unroll
            for (int t = 0; t < 16; t++) {
                float v0 = h1[2 * t], v1 = h1[2 * t + 1];
                __half2 hh = __floats2half2_rn(v0, v1);
                float2 fb = __half22float2(hh);
                __half2 ll = __floats2half2_rn(v0 - fb.x, v1 - fb.y);
                *(u32*)(arow + 4 * t) = *(u32*)&hh;
                *(u32*)(arow + 64 + 4 * t) = *(u32*)&ll;
            }
        }
        // x[src] -> xs
        if (valid) {
            const float4* xr = (const float4*)(g_x + (size_t)si * 32);
            float* xd = xw + lane * 33;
#pragma unroll
            for (int t = 0; t < 8; t++) {
                float4 v = xr[t];
                xd[4 * t + 0] = v.x;
                xd[4 * t + 1] = v.y;
                xd[4 * t + 2] = v.z;
                xd[4 * t + 3] = v.w;
            }
        }
        __syncwarp();

        // ================= h2 GEMM: h2 = relu(h1 @ W2 + b2) =================
        // h1 fragments (2-split)
        u32 A1h[2][2][4], A1l[2][2][4];
#pragma unroll
        for (int mt = 0; mt < 2; mt++)
#pragma unroll
            for (int kk = 0; kk < 2; kk++) {
                u32 a = aw + (u32)((mt * 16 + rowoff) * A_STRIDE) +
                        (u32)(kk * 32 + colb16);
                ldsm_x4(A1h[mt][kk], a);
                ldsm_x4(A1l[mt][kk], a + 64);
            }

#pragma unroll
        for (int ni = 0; ni < 2; ni++) {
            u32 bch = sb + OFF_W2H + (u32)(ni * 32 + colb16);
            u32 bcl = sb + OFF_W2L + (u32)(ni * 32 + colb16);
            u32 b0h[4], b1h[4], b0l[4], b1l[4];
            ldsm_x4t(b0h, bch + (u32)(rowoff * W2_STRIDE));
            ldsm_x4t(b1h, bch + (u32)((rowoff + 16) * W2_STRIDE));
            ldsm_x4t(b0l, bcl + (u32)(rowoff * W2_STRIDE));
            ldsm_x4t(b1l, bcl + (u32)((rowoff + 16) * W2_STRIDE));

            float a2[2][2][4];
#pragma unroll
            for (int n8l = 0; n8l < 2; n8l++) {
                float2 bb = *(const float2*)(smf + F_B2 +
                                             (ni * 2 + n8l) * 8 + 2 * tq);
#pragma unroll
                for (int mt = 0; mt < 2; mt++) {
                    a2[mt][n8l][0] = bb.x;
                    a2[mt][n8l][1] = bb.y;
                    a2[mt][n8l][2] = bb.x;
                    a2[mt][n8l][3] = bb.y;
                }
            }
            // 24 mma: (A1h+A1l)@W2h + A1h@W2l, k16 x2
            mma_f16(a2[0][0], A1h[0][0], b0h[0], b0h[1]);
            mma_f16(a2[0][1], A1h[0][0], b0h[2], b0h[3]);
            mma_f16(a2[1][0], A1h[1][0], b0h[0], b0h[1]);
            mma_f16(a2[1][1], A1h[1][0], b0h[2], b0h[3]);
            mma_f16(a2[0][0], A1h[0][1], b1h[0], b1h[1]);
            mma_f16(a2[0][1], A1h[0][1], b1h[2], b1h[3]);
            mma_f16(a2[1][0], A1h[1][1], b1h[0], b1h[1]);
            mma_f16(a2[1][1], A1h[1][1], b1h[2], b1h[3]);
            mma_f16(a2[0][0], A1l[0][0], b0h[0], b0h[1]);
            mma_f16(a2[0][1], A1l[0][0], b0h[2], b0h[3]);
            mma_f16(a2[1][0], A1l[1][0], b0h[0], b0h[1]);
            mma_f16(a2[1][1], A1l[1][0], b0h[2], b0h[3]);
            mma_f16(a2[0][0], A1l[0][1], b1h[0], b1h[1]);
            mma_f16(a2[0][1], A1l[0][1], b1h[2], b1h[3]);
            mma_f16(a2[1][0], A1l[1][1], b1h[0], b1h[1]);
            mma_f16(a2[1][1], A1l[1][1], b1h[2], b1h[3]);
            mma_f16(a2[0][0], A1h[0][0], b0l[0], b0l[1]);
            mma_f16(a2[0][1], A1h[0][0], b0l[2], b0l[3]);
            mma_f16(a2[1][0], A1h[1][0], b0l[0], b0l[1]);
            mma_f16(a2[1][1], A1h[1][0], b0l[2], b0l[3]);
            mma_f16(a2[0][0], A1h[0][1], b1l[0], b1l[1]);
            mma_f16(a2[0][1], A1h[0][1], b1l[2], b1l[3]);
            mma_f16(a2[1][0], A1h[1][1], b1l[0], b1l[1]);
            mma_f16(a2[1][1], A1h[1][1], b1l[2], b1l[3]);

            // write-out: relu, fp16 2-split back into A rows (cols ni*16..)
#pragma unroll
            for (int mt = 0; mt < 2; mt++)
#pragma unroll
                for (int n8l = 0; n8l < 2; n8l++) {
                    int cbyte = ((ni * 2 + n8l) * 8 + 2 * tq) * 2;
                    char* r0p = arow_base +
                                (mt * 16 + g) * A_STRIDE + cbyte;
                    char* r8p = r0p + 8 * A_STRIDE;
                    const float* d = a2[mt][n8l];
                    float f0 = fmaxf(d[0], 0.f), f1 = fmaxf(d[1], 0.f);
                    float f2 = fmaxf(d[2], 0.f), f3 = fmaxf(d[3], 0.f);
                    __half2 h0 = __floats2half2_rn(f0, f1);
                    float2 fb0 = __half22float2(h0);
                    __half2 l0 = __floats2half2_rn(f0 - fb0.x, f1 - fb0.y);
                    __half2 h8 = __floats2half2_rn(f2, f3);
                    float2 fb8 = __half22float2(h8);
                    __half2 l8 = __floats2half2_rn(f2 - fb8.x, f3 - fb8.y);
                    *(u32*)r0p = *(u32*)&h0;
                    *(u32*)(r0p + 64) = *(u32*)&l0;
                    *(u32*)r8p = *(u32*)&h8;
                    *(u32*)(r8p + 64) = *(u32*)&l8;
                }
        }
        __syncwarp();

        // ================= main A fragments (h2 2-split) =================
        u32 Ah[2][2][4], Al[2][2][4];
#pragma unroll
        for (int mt = 0; mt < 2; mt++)
#pragma unroll
            for (int kk = 0; kk < 2; kk++) {
                u32 a = aw + (u32)((mt * 16 + rowoff) * A_STRIDE) +
                        (u32)(kk * 32 + colb16);
                ldsm_x4(Ah[mt][kk], a);
                ldsm_x4(Al[mt][kk], a + 64);
            }

        ull msg[2][2][4];
#pragma unroll
        for (int a = 0; a < 2; a++)
#pragma unroll
            for (int bq = 0; bq < 2; bq++)
#pragma unroll
                for (int t = 0; t < 4; t++) msg[a][bq][t] = 0ull;

        // ================= 32 chunks of n=32 (chunk == h) =================
#pragma unroll 1
        for (int c = 0; c < 32; c++) {
            const int cb = c * 32;
            u32 bb0[4], bb1[4], bb2[4], bb3r[4];   // [ni][k16]
            u32 bcol0 = sb + OFF_B + (u32)(cb * 2 + colb16);
            u32 bcol1 = bcol0 + 32;
            ldsm_x4t(bb0, bcol0 + (u32)(rowoff * B_STRIDE));
            ldsm_x4t(bb1, bcol0 + (u32)((rowoff + 16) * B_STRIDE));
            ldsm_x4t(bb2, bcol1 + (u32)(rowoff * B_STRIDE));
            ldsm_x4t(bb3r, bcol1 + (u32)((rowoff + 16) * B_STRIDE));

            float acc[2][4][4];
#pragma unroll
            for (int n8 = 0; n8 < 4; n8++) {
                float2 bv = *(const float2*)(smf + F_B3S + cb + n8 * 8 + 2 * tq);
#pragma unroll
                for (int mt = 0; mt < 2; mt++) {
                    acc[mt][n8][0] = bv.x;
                    acc[mt][n8][1] = bv.y;
                    acc[mt][n8][2] = bv.x;
                    acc[mt][n8][3] = bv.y;
                }
            }
            // 32 mma interleaved across 8 chains
            mma_f16(acc[0][0], Ah[0][0], bb0[0], bb0[1]);
            mma_f16(acc[0][1], Ah[0][0], bb0[2], bb0[3]);
            mma_f16(acc[1][0], Ah[1][0], bb0[0], bb0[1]);
            mma_f16(acc[1][1], Ah[1][0], bb0[2], bb0[3]);
            mma_f16(acc[0][2], Ah[0][0], bb2[0], bb2[1]);
            mma_f16(acc[0][3], Ah[0][0], bb2[2], bb2[3]);
            mma_f16(acc[1][2], Ah[1][0], bb2[0], bb2[1]);
            mma_f16(acc[1][3], Ah[1][0], bb2[2], bb2[3]);
            mma_f16(acc[0][0], Ah[0][1], bb1[0], bb1[1]);
            mma_f16(acc[0][1], Ah[0][1], bb1[2], bb1[3]);
            mma_f16(acc[1][0], Ah[1][1], bb1[0], bb1[1]);
            mma_f16(acc[1][1], Ah[1][1], bb1[2], bb1[3]);
            mma_f16(acc[0][2], Ah[0][1], bb3r[0], bb3r[1]);
            mma_f16(acc[0][3], Ah[0][1], bb3r[2], bb3r[3]);
            mma_f16(acc[1][2], Ah[1][1], bb3r[0], bb3r[1]);
            mma_f16(acc[1][3], Ah[1][1], bb3r[2], bb3r[3]);
            mma_f16(acc[0][0], Al[0][0], bb0[0], bb0[1]);
            mma_f16(acc[0][1], Al[0][0], bb0[2], bb0[3]);
            mma_f16(acc[1][0], Al[1][0], bb0[0], bb0[1]);
            mma_f16(acc[1][1], Al[1][0], bb0[2], bb0[3]);
            mma_f16(acc[0][2], Al[0][0], bb2[0], bb2[1]);
            mma_f16(acc[0][3], Al[0][0], bb2[2], bb2[3]);
            mma_f16(acc[1][2], Al[1][0], bb2[0], bb2[1]);
            mma_f16(acc[1][3], Al[1][0], bb2[2], bb2[3]);
            mma_f16(acc[0][0], Al[0][1], bb1[0], bb1[1]);
            mma_f16(acc[0][1], Al[0][1], bb1[2], bb1[3]);
            mma_f16(acc[1][0], Al[1][1], bb1[0], bb1[1]);
            mma_f16(acc[1][1], Al[1][1], bb1[2], bb1[3]);
            mma_f16(acc[0][2], Al[0][1], bb3r[0], bb3r[1]);
            mma_f16(acc[0][3], Al[0][1], bb3r[2], bb3r[3]);
            mma_f16(acc[1][2], Al[1][1], bb3r[0], bb3r[1]);
            mma_f16(acc[1][3], Al[1][1], bb3r[2], bb3r[3]);

            // epilogue: msg += x_h * relu(acc)
#pragma unroll
            for (int mt = 0; mt < 2; mt++) {
                float x0 = xw[(mt * 16 + g) * 33 + c];
                float x1 = xw[(mt * 16 + 8 + g) * 33 + c];
                ull xp0 = pack2(x0, x0);
                ull xp1 = pack2(x1, x1);
#pragma unroll
                for (int t = 0; t < 4; t++) {
                    const float* d = acc[mt][t];
                    float f0 = fmaxf(d[0], 0.f), f1 = fmaxf(d[1], 0.f);
                    float f2 = fmaxf(d[2], 0.f), f3 = fmaxf(d[3], 0.f);
                    fma2(msg[mt][0][t], pack2(f0, f1), xp0);
                    fma2(msg[mt][1][t], pack2(f2, f3), xp1);
                }
            }
        }

        // ================= scatter =================
#pragma unroll
        for (int mt = 0; mt < 2; mt++)
#pragma unroll
            for (int hf = 0; hf < 2; hf++) {
                int row = mt * 16 + hf * 8 + g;
                int d = dstw[row];
                if (d >= 0) {
                    float* ap = g_agg + (size_t)d * 32 + 2 * tq;
#pragma unroll
                    for (int t = 0; t < 4; t++) {
                        float m0, m1;
                        unpack2(msg[mt][hf][t], m0, m1);
                        atomicAdd(ap + 8 * t, m0);
                        atomicAdd(ap + 8 * t + 1, m1);
                    }
                }
            }
        __syncwarp();
    }
}

// ---------------------------------------------------------------------------
__global__ void node_kernel(const float* __restrict__ conv_b, int N) {
    int idx = blockIdx.x * blockDim.x + threadIdx.x;
    if (idx < N * 32) {
        float v = g_agg[idx] + conv_b[idx & 31];
        g_x[idx] += fmaxf(v, 0.f);
        g_agg[idx] = 0.f;
    }
}

__global__ void pool_kernel(const int* __restrict__ batch_ids, int N) {
    int idx = blockIdx.x * blockDim.x + threadIdx.x;
    if (idx < N * 32) {
        int n = idx >> 5, k = idx & 31;
        int b = batch_ids[n];
        atomicAdd(&g_pooled[b * 32 + k], g_x[idx]);
        if (k == 0) atomicAdd(&g_counts[b], 1.f);
    }
}

__device__ __forceinline__ float selu_f(float x) {
    const float alpha = 1.6732632423543772f;
    const float scale = 1.0507009873554805f;
    return x > 0.f ? scale * x : scale * alpha * expm1f(x);
}

__global__ void mlp_kernel(const float* __restrict__ W1,
                           const float* __restrict__ b1,
                           const float* __restrict__ W2,
                           const float* __restrict__ b2,
                           const float* __restrict__ W3,
                           const float* __restrict__ b3,
                           const float* __restrict__ W4,
                           const float* __restrict__ b4,
                           float* __restrict__ out) {
    __shared__ float sbuf[32][280];
    int warp = threadIdx.x >> 5, lane = threadIdx.x & 31;
    int b = blockIdx.x * 32 + warp;
    if (b >= BATCH) return;
    float* buf = sbuf[warp];

    float cnt = fmaxf(g_counts[b], 1.f);
    buf[lane] = g_pooled[b * 32 + lane] / cnt;
    __syncwarp();

#pragma unroll
    for (int r = 0; r < 4; r++) {
        int o = lane + 32 * r;
        float a = b1[o];
        for (int k = 0; k < 32; k++) a = fmaf(buf[k], W1[k * 128 + o], a);
        buf[32 + o] = selu_f(a);
    }
    __syncwarp();
#pragma unroll
    for (int r = 0; r < 2; r++) {
        int o = lane + 32 * r;
        float a = b2[o];
        for (int k = 0; k < 128; k++) a = fmaf(buf[32 + k], W2[k * 64 + o], a);
        buf[160 + o] = selu_f(a);
    }
    __syncwarp();
    {
        int o = lane;
        float a = b3[o];
        for (int k = 0; k < 64; k++) a = fmaf(buf[160 + k], W3[k * 32 + o], a);
        buf[224 + o] = selu_f(a);
    }
    __syncwarp();
    if (lane < 21) {
        float a = b4[lane];
        for (int k = 0; k < 32; k++) a = fmaf(buf[224 + k], W4[k * 21 + lane], a);
        buf[256 + lane] = a;
    }
    __syncwarp();
    for (int r = lane; r < 36; r += 32) out[b * 36 + r] = buf[256 + c_IDX[r]];
}

// ---------------------------------------------------------------------------
extern "C" void kernel_launch(void* const* d_in, const int* in_sizes, int n_in,
                              void* d_out, int out_size) {
    const float* node_attrs = (const float*)d_in[0];
    const float* positions = (const float*)d_in[1];
    const float* shifts = (const float*)d_in[2];
    const float* edge_attr = (const float*)d_in[3];
    const int* edge_index = (const int*)d_in[4];
    const int* batch_ids = (const int*)d_in[5];
    const float* embed_W = (const float*)d_in[6];
    const float* embed_b = (const float*)d_in[7];
    const float* e_W1 = (const float*)d_in[8];
    const float* e_b1 = (const float*)d_in[9];
    const float* e_W2 = (const float*)d_in[10];
    const float* e_b2 = (const float*)d_in[11];
    const float* e_W3 = (const float*)d_in[12];
    const float* e_b3 = (const float*)d_in[13];
    const float* conv_b = (const float*)d_in[14];
    const float* h_W1 = (const float*)d_in[15];
    const float* h_b1 = (const float*)d_in[16];
    const float* h_W2 = (const float*)d_in[17];
    const float* h_b2 = (const float*)d_in[18];
    const float* h_W3 = (const float*)d_in[19];
    const float* h_b3 = (const float*)d_in[20];
    const float* h_W4 = (const float*)d_in[21];
    const float* h_b4 = (const float*)d_in[22];

    int N = in_sizes[0];
    int E = in_sizes[3];
    if (N > NMAX) N = NMAX;
    if (E > EMAX) E = EMAX;

    cudaFuncSetAttribute(edge_kernel,
                         cudaFuncAttributeMaxDynamicSharedMemorySize,
                         SMEM_TOTAL);

    int tot = N * 32;
    int blk = 256;
    init_kernel<<<(tot + blk - 1) / blk, blk>>>(node_attrs, embed_W, embed_b, N);

    for (int l = 0; l < 3; l++) {
        edge_kernel<<<148, NTHREADS, SMEM_TOTAL>>>(
            positions, shifts, edge_attr, edge_index, e_W1 + l * 160,
            e_b1 + l * 32, e_W2 + l * 1024, e_b2 + l * 32, e_W3 + l * 32768,
            e_b3 + l * 1024, E);
        node_kernel<<<(tot + blk - 1) / blk, blk>>>(conv_b + l * 32, N);
    }

    pool_kernel<<<(tot + blk - 1) / blk, blk>>>(batch_ids, N);
    mlp_kernel<<<2, 1024>>>(h_W1, h_b1, h_W2, h_b2, h_W3, h_b3, h_W4, h_b4,
                            (float*)d_out);
}

// round 8
// speedup vs baseline: 4.5209x; 1.2330x over previous
#include <cuda_runtime.h>
#include <cuda_fp16.h>
#include <math.h>

// ---------------------------------------------------------------------------
// NNConvNet fused GNN — R7: single-split A for W3 GEMM (16 mma/chunk),
// scalar FFMA epilogue (no f32x2 packing), double-buffered B fragments.
//  phase1 (thread=edge): ef -> h1 (fp32); h1 -> fp16 2-split A row.
//  h2 GEMM: h2 = relu(h1 @ W2 + b2) via HMMA (h1 2-split x W2 2-split);
//           relu'd result written back (fp16, high only) as A rows.
//  W3 GEMM: D[32x1024] = h2 @ W3 (fp16 x fp16), 32 chunks of n=32 (chunk==h);
//           acc init = b3; B frags prefetched one chunk ahead;
//           epi: msg[k] += x_h * relu(acc), scalar FMNMX+FFMA.
//  scatter: 32 atomicAdd per lane.
// ---------------------------------------------------------------------------

#define NMAX 20000
#define EMAX 320000
#define BATCH 64
#define NWARPS 14
#define NTHREADS (NWARPS * 32)

typedef unsigned int u32;
typedef unsigned short u16;

__device__ float g_x[NMAX * 32];
__device__ float g_agg[NMAX * 32];
__device__ float g_pooled[BATCH * 32];
__device__ float g_counts[BATCH];

__constant__ int c_IDX[36] = {
    0, 1, 2,  3,  4,  5,
    1, 6, 7,  8,  9,  10,
    2, 7, 11, 12, 13, 14,
    3, 8, 12, 15, 16, 17,
    4, 9, 13, 16, 18, 19,
    5, 10,14, 17, 19, 20};

// ---------------- smem layout ----------------
// floats:
#define F_W1 0        // 160
#define F_B1 160      // 32
#define F_B2 192      // 32
#define F_B3S 224     // 1024 (ends 1248 floats = 4992 B)
// bytes:
#define OFF_W2H 4992                  // 32 rows * 80 B = 2560
#define OFF_W2L 7552                  // 2560
#define OFF_DSTS 10112                // 14*32*4 = 1792
#define OFF_XS 11904                  // 14*32*33*4 = 59136
#define OFF_A 71040                   // 14*32*144 = 64512
#define OFF_B 135552                  // 32*2064 = 66048
#define A_STRIDE 144
#define B_STRIDE 2064
#define W2_STRIDE 80
#define SMEM_TOTAL 201600

// ---------------- PTX helpers ----------------
__device__ __forceinline__ u32 smem_u32(const void* p) {
    u32 a;
    asm("{ .reg .u64 t; cvta.to.shared.u64 t, %1; cvt.u32.u64 %0, t; }"
        : "=r"(a) : "l"(p));
    return a;
}
__device__ __forceinline__ void ldsm_x4(u32* r, u32 addr) {
    asm volatile(
        "ldmatrix.sync.aligned.m8n8.x4.shared.b16 {%0,%1,%2,%3}, [%4];"
        : "=r"(r[0]), "=r"(r[1]), "=r"(r[2]), "=r"(r[3]) : "r"(addr));
}
__device__ __forceinline__ void ldsm_x4t(u32* r, u32 addr) {
    asm volatile(
        "ldmatrix.sync.aligned.m8n8.x4.trans.shared.b16 {%0,%1,%2,%3}, [%4];"
        : "=r"(r[0]), "=r"(r[1]), "=r"(r[2]), "=r"(r[3]) : "r"(addr));
}
__device__ __forceinline__ void mma_f16(float* d, const u32* a, u32 b0,
                                        u32 b1) {
    asm volatile(
        "mma.sync.aligned.m16n8k16.row.col.f32.f16.f16.f32 "
        "{%0,%1,%2,%3}, {%4,%5,%6,%7}, {%8,%9}, {%0,%1,%2,%3};"
        : "+f"(d[0]), "+f"(d[1]), "+f"(d[2]), "+f"(d[3])
        : "r"(a[0]), "r"(a[1]), "r"(a[2]), "r"(a[3]), "r"(b0), "r"(b1));
}

// ---------------------------------------------------------------------------
__global__ void init_kernel(const float* __restrict__ node_attrs,
                            const float* __restrict__ embW,
                            const float* __restrict__ embB, int N) {
    int idx = blockIdx.x * blockDim.x + threadIdx.x;
    if (idx < N * 32) {
        int k = idx & 31;
        g_x[idx] = fmaf(node_attrs[idx >> 5], embW[k], embB[k]);
        g_agg[idx] = 0.f;
    }
    if (idx < BATCH * 32) g_pooled[idx] = 0.f;
    if (idx < BATCH) g_counts[idx] = 0.f;
}

// ---------------------------------------------------------------------------
__global__ void __launch_bounds__(NTHREADS, 1)
edge_kernel(const float* __restrict__ positions,
            const float* __restrict__ shifts,
            const float* __restrict__ edge_attr,
            const int* __restrict__ eidx,
            const float* __restrict__ W1, const float* __restrict__ b1,
            const float* __restrict__ W2, const float* __restrict__ b2,
            const float* __restrict__ W3, const float* __restrict__ b3,
            int E) {
    extern __shared__ float smf[];
    char* smc = (char*)smf;
    const u32 sb = smem_u32(smf);
    const int tid = threadIdx.x;
    const int lane = tid & 31;
    const int warp = tid >> 5;

    // ---- stage B = fp16(W3) in [j][n] layout ----
    for (int i = tid; i < 32768; i += NTHREADS) {
        int j = i >> 10, col = i & 1023;
        __half h = __float2half_rn(W3[i]);
        *(u16*)(smc + OFF_B + j * B_STRIDE + col * 2) = *(u16*)&h;
    }
    // ---- W2 fp16 2-split [j][n] ----
    for (int i = tid; i < 1024; i += NTHREADS) {
        int j = i >> 5, n = i & 31;
        float w = W2[i];
        __half hh = __float2half_rn(w);
        __half ll = __float2half_rn(w - __half2float(hh));
        *(u16*)(smc + OFF_W2H + j * W2_STRIDE + n * 2) = *(u16*)&hh;
        *(u16*)(smc + OFF_W2L + j * W2_STRIDE + n * 2) = *(u16*)&ll;
        smf[F_B3S + i] = b3[i];
    }
    if (tid < 160) smf[F_W1 + tid] = W1[tid];
    if (tid < 32) {
        smf[F_B1 + tid] = b1[tid];
        smf[F_B2 + tid] = b2[tid];
    }
    __syncthreads();

    const int g = lane >> 2;     // fragment row group
    const int tq = lane & 3;     // fragment col group
    char* arow_base = smc + OFF_A + (warp * 32) * A_STRIDE;
    const u32 aw = sb + OFF_A + (u32)(warp * 32) * A_STRIDE;
    float* xw = (float*)(smc + OFF_XS) + warp * (32 * 33);
    int* dstw = (int*)(smc + OFF_DSTS) + warp * 32;

    const int rowoff = ((lane >> 3) & 1) * 8 + (lane & 7);
    const int colb16 = (lane >> 4) * 16;

    const int* srcp = eidx;
    const int* dstp = eidx + E;
    const int ntiles = (E + 31) >> 5;
    const int gw = blockIdx.x * NWARPS + warp;
    const int gstride = gridDim.x * NWARPS;

// prefetch one chunk's 4 B fragments
#define LOADB(FR, C)                                                        \
    do {                                                                    \
        u32 _bc = sb + OFF_B + (u32)((C) * 64 + colb16);                    \
        ldsm_x4t(FR[0], _bc + (u32)(rowoff * B_STRIDE));                    \
        ldsm_x4t(FR[1], _bc + (u32)((rowoff + 16) * B_STRIDE));             \
        ldsm_x4t(FR[2], _bc + 32 + (u32)(rowoff * B_STRIDE));               \
        ldsm_x4t(FR[3], _bc + 32 + (u32)((rowoff + 16) * B_STRIDE));        \
    } while (0)

#define CHUNK_BODY(BB, C)                                                   \
    do {                                                                    \
        const int _cb = (C) * 32;                                           \
        float acc[2][4][4];                                                 \
        _Pragma("unroll") for (int n8 = 0; n8 < 4; n8++) {                  \
            float2 bv =                                                     \
                *(const float2*)(smf + F_B3S + _cb + n8 * 8 + 2 * tq);      \
            _Pragma("unroll") for (int mt = 0; mt < 2; mt++) {              \
                acc[mt][n8][0] = bv.x;                                      \
                acc[mt][n8][1] = bv.y;                                      \
                acc[mt][n8][2] = bv.x;                                      \
                acc[mt][n8][3] = bv.y;                                      \
            }                                                               \
        }                                                                   \
        mma_f16(acc[0][0], Ah[0][0], BB[0][0], BB[0][1]);                   \
        mma_f16(acc[0][1], Ah[0][0], BB[0][2], BB[0][3]);                   \
        mma_f16(acc[1][0], Ah[1][0], BB[0][0], BB[0][1]);                   \
        mma_f16(acc[1][1], Ah[1][0], BB[0][2], BB[0][3]);                   \
        mma_f16(acc[0][2], Ah[0][0], BB[2][0], BB[2][1]);                   \
        mma_f16(acc[0][3], Ah[0][0], BB[2][2], BB[2][3]);                   \
        mma_f16(acc[1][2], Ah[1][0], BB[2][0], BB[2][1]);                   \
        mma_f16(acc[1][3], Ah[1][0], BB[2][2], BB[2][3]);                   \
        mma_f16(acc[0][0], Ah[0][1], BB[1][0], BB[1][1]);                   \
        mma_f16(acc[0][1], Ah[0][1], BB[1][2], BB[1][3]);                   \
        mma_f16(acc[1][0], Ah[1][1], BB[1][0], BB[1][1]);                   \
        mma_f16(acc[1][1], Ah[1][1], BB[1][2], BB[1][3]);                   \
        mma_f16(acc[0][2], Ah[0][1], BB[3][0], BB[3][1]);                   \
        mma_f16(acc[0][3], Ah[0][1], BB[3][2], BB[3][3]);                   \
        mma_f16(acc[1][2], Ah[1][1], BB[3][0], BB[3][1]);                   \
        mma_f16(acc[1][3], Ah[1][1], BB[3][2], BB[3][3]);                   \
        _Pragma("unroll") for (int mt = 0; mt < 2; mt++) {                  \
            float x0 = xw[(mt * 16 + g) * 33 + (C)];                        \
            float x1 = xw[(mt * 16 + 8 + g) * 33 + (C)];                    \
            _Pragma("unroll") for (int t = 0; t < 4; t++) {                 \
                const float* d = acc[mt][t];                                \
                msg[mt][0][2 * t] =                                         \
                    fmaf(x0, fmaxf(d[0], 0.f), msg[mt][0][2 * t]);          \
                msg[mt][0][2 * t + 1] =                                     \
                    fmaf(x0, fmaxf(d[1], 0.f), msg[mt][0][2 * t + 1]);      \
                msg[mt][1][2 * t] =                                         \
                    fmaf(x1, fmaxf(d[2], 0.f), msg[mt][1][2 * t]);          \
                msg[mt][1][2 * t + 1] =                                     \
                    fmaf(x1, fmaxf(d[3], 0.f), msg[mt][1][2 * t + 1]);      \
            }                                                               \
        }                                                                   \
    } while (0)

    for (int tile = gw; tile < ntiles; tile += gstride) {
        // ================= phase 1: thread = edge, h1 only =================
        int e = (tile << 5) + lane;
        bool valid = e < E;
        float vx = 0.f, vy = 0.f, vz = 0.f, ea = 0.f;
        int si = 0, di = -1;
        if (valid) {
            si = srcp[e];
            di = dstp[e];
            float px = positions[si * 3 + 0], py = positions[si * 3 + 1],
                  pz = positions[si * 3 + 2];
            float qx = positions[di * 3 + 0], qy = positions[di * 3 + 1],
                  qz = positions[di * 3 + 2];
            vx = qx - px + shifts[e * 3 + 0];
            vy = qy - py + shifts[e * 3 + 1];
            vz = qz - pz + shifts[e * 3 + 2];
            ea = edge_attr[e];
        }
        dstw[lane] = valid ? di : -1;
        float len = sqrtf(vx * vx + vy * vy + vz * vz);

        float h1[32];
#pragma unroll
        for (int k = 0; k < 32; k++) {
            float a = smf[F_B1 + k];
            a = fmaf(vx, smf[F_W1 + 0 * 32 + k], a);
            a = fmaf(vy, smf[F_W1 + 1 * 32 + k], a);
            a = fmaf(vz, smf[F_W1 + 2 * 32 + k], a);
            a = fmaf(len, smf[F_W1 + 3 * 32 + k], a);
            a = fmaf(ea, smf[F_W1 + 4 * 32 + k], a);
            h1[k] = fmaxf(a, 0.f);
        }

        // h1 -> fp16 2-split A row [h1h(32)|h1l(32)]
        {
            char* arow = arow_base + lane * A_STRIDE;
#pragma unroll
            for (int t = 0; t < 16; t++) {
                float v0 = h1[2 * t], v1 = h1[2 * t + 1];
                __half2 hh = __floats2half2_rn(v0, v1);
                float2 fb = __half22float2(hh);
                __half2 ll = __floats2half2_rn(v0 - fb.x, v1 - fb.y);
                *(u32*)(arow + 4 * t) = *(u32*)&hh;
                *(u32*)(arow + 64 + 4 * t) = *(u32*)&ll;
            }
        }
        // x[src] -> xs
        if (valid) {
            const float4* xr = (const float4*)(g_x + (size_t)si * 32);
            float* xd = xw + lane * 33;
#pragma unroll
            for (int t = 0; t < 8; t++) {
                float4 v = xr[t];
                xd[4 * t + 0] = v.x;
                xd[4 * t + 1] = v.y;
                xd[4 * t + 2] = v.z;
                xd[4 * t + 3] = v.w;
            }
        }
        __syncwarp();

        // ================= h2 GEMM: h2 = relu(h1 @ W2 + b2) =================
        {
            u32 A1h[2][2][4], A1l[2][2][4];
#pragma unroll
            for (int mt = 0; mt < 2; mt++)
#pragma unroll
                for (int kk = 0; kk < 2; kk++) {
                    u32 a = aw + (u32)((mt * 16 + rowoff) * A_STRIDE) +
                            (u32)(kk * 32 + colb16);
                    ldsm_x4(A1h[mt][kk], a);
                    ldsm_x4(A1l[mt][kk], a + 64);
                }

#pragma unroll
            for (int ni = 0; ni < 2; ni++) {
                u32 bch = sb + OFF_W2H + (u32)(ni * 32 + colb16);
                u32 bcl = sb + OFF_W2L + (u32)(ni * 32 + colb16);
                u32 b0h[4], b1h[4], b0l[4], b1l[4];
                ldsm_x4t(b0h, bch + (u32)(rowoff * W2_STRIDE));
                ldsm_x4t(b1h, bch + (u32)((rowoff + 16) * W2_STRIDE));
                ldsm_x4t(b0l, bcl + (u32)(rowoff * W2_STRIDE));
                ldsm_x4t(b1l, bcl + (u32)((rowoff + 16) * W2_STRIDE));

                float a2[2][2][4];
#pragma unroll
                for (int n8l = 0; n8l < 2; n8l++) {
                    float2 bb = *(const float2*)(smf + F_B2 +
                                                 (ni * 2 + n8l) * 8 + 2 * tq);
#pragma unroll
                    for (int mt = 0; mt < 2; mt++) {
                        a2[mt][n8l][0] = bb.x;
                        a2[mt][n8l][1] = bb.y;
                        a2[mt][n8l][2] = bb.x;
                        a2[mt][n8l][3] = bb.y;
                    }
                }
                mma_f16(a2[0][0], A1h[0][0], b0h[0], b0h[1]);
                mma_f16(a2[0][1], A1h[0][0], b0h[2], b0h[3]);
                mma_f16(a2[1][0], A1h[1][0], b0h[0], b0h[1]);
                mma_f16(a2[1][1], A1h[1][0], b0h[2], b0h[3]);
                mma_f16(a2[0][0], A1h[0][1], b1h[0], b1h[1]);
                mma_f16(a2[0][1], A1h[0][1], b1h[2], b1h[3]);
                mma_f16(a2[1][0], A1h[1][1], b1h[0], b1h[1]);
                mma_f16(a2[1][1], A1h[1][1], b1h[2], b1h[3]);
                mma_f16(a2[0][0], A1l[0][0], b0h[0], b0h[1]);
                mma_f16(a2[0][1], A1l[0][0], b0h[2], b0h[3]);
                mma_f16(a2[1][0], A1l[1][0], b0h[0], b0h[1]);
                mma_f16(a2[1][1], A1l[1][0], b0h[2], b0h[3]);
                mma_f16(a2[0][0], A1l[0][1], b1h[0], b1h[1]);
                mma_f16(a2[0][1], A1l[0][1], b1h[2], b1h[3]);
                mma_f16(a2[1][0], A1l[1][1], b1h[0], b1h[1]);
                mma_f16(a2[1][1], A1l[1][1], b1h[2], b1h[3]);
                mma_f16(a2[0][0], A1h[0][0], b0l[0], b0l[1]);
                mma_f16(a2[0][1], A1h[0][0], b0l[2], b0l[3]);
                mma_f16(a2[1][0], A1h[1][0], b0l[0], b0l[1]);
                mma_f16(a2[1][1], A1h[1][0], b0l[2], b0l[3]);
                mma_f16(a2[0][0], A1h[0][1], b1l[0], b1l[1]);
                mma_f16(a2[0][1], A1h[0][1], b1l[2], b1l[3]);
                mma_f16(a2[1][0], A1h[1][1], b1l[0], b1l[1]);
                mma_f16(a2[1][1], A1h[1][1], b1l[2], b1l[3]);

                // write-out: relu -> fp16 (high only; W3 GEMM is single-split)
#pragma unroll
                for (int mt = 0; mt < 2; mt++)
#pragma unroll
                    for (int n8l = 0; n8l < 2; n8l++) {
                        int cbyte = ((ni * 2 + n8l) * 8 + 2 * tq) * 2;
                        char* r0p =
                            arow_base + (mt * 16 + g) * A_STRIDE + cbyte;
                        char* r8p = r0p + 8 * A_STRIDE;
                        const float* d = a2[mt][n8l];
                        float f0 = fmaxf(d[0], 0.f), f1 = fmaxf(d[1], 0.f);
                        float f2 = fmaxf(d[2], 0.f), f3 = fmaxf(d[3], 0.f);
                        __half2 h0 = __floats2half2_rn(f0, f1);
                        __half2 h8 = __floats2half2_rn(f2, f3);
                        *(u32*)r0p = *(u32*)&h0;
                        *(u32*)r8p = *(u32*)&h8;
                    }
            }
        }
        __syncwarp();

        // ================= main A fragments (h2 fp16, single split) ========
        u32 Ah[2][2][4];
#pragma unroll
        for (int mt = 0; mt < 2; mt++)
#pragma unroll
            for (int kk = 0; kk < 2; kk++) {
                u32 a = aw + (u32)((mt * 16 + rowoff) * A_STRIDE) +
                        (u32)(kk * 32 + colb16);
                ldsm_x4(Ah[mt][kk], a);
            }

        float msg[2][2][8];
#pragma unroll
        for (int a = 0; a < 2; a++)
#pragma unroll
            for (int hf = 0; hf < 2; hf++)
#pragma unroll
                for (int t = 0; t < 8; t++) msg[a][hf][t] = 0.f;

        // ============ 32 chunks of n=32 (chunk == h), B prefetched ==========
        u32 bbA[4][4], bbB[4][4];
        LOADB(bbA, 0);
#pragma unroll 1
        for (int c = 0; c < 32; c += 2) {
            LOADB(bbB, c + 1);
            CHUNK_BODY(bbA, c);
            if (c + 2 < 32) LOADB(bbA, c + 2);
            CHUNK_BODY(bbB, c + 1);
        }

        // ================= scatter =================
#pragma unroll
        for (int mt = 0; mt < 2; mt++)
#pragma unroll
            for (int hf = 0; hf < 2; hf++) {
                int row = mt * 16 + hf * 8 + g;
                int d = dstw[row];
                if (d >= 0) {
                    float* ap = g_agg + (size_t)d * 32 + 2 * tq;
#pragma unroll
                    for (int t = 0; t < 4; t++) {
                        atomicAdd(ap + 8 * t, msg[mt][hf][2 * t]);
                        atomicAdd(ap + 8 * t + 1, msg[mt][hf][2 * t + 1]);
                    }
                }
            }
        __syncwarp();
    }
#undef LOADB
#undef CHUNK_BODY
}

// ---------------------------------------------------------------------------
__global__ void node_kernel(const float* __restrict__ conv_b, int N) {
    int idx = blockIdx.x * blockDim.x + threadIdx.x;
    if (idx < N * 32) {
        float v = g_agg[idx] + conv_b[idx & 31];
        g_x[idx] += fmaxf(v, 0.f);
        g_agg[idx] = 0.f;
    }
}

__global__ void pool_kernel(const int* __restrict__ batch_ids, int N) {
    int idx = blockIdx.x * blockDim.x + threadIdx.x;
    if (idx < N * 32) {
        int n = idx >> 5, k = idx & 31;
        int b = batch_ids[n];
        atomicAdd(&g_pooled[b * 32 + k], g_x[idx]);
        if (k == 0) atomicAdd(&g_counts[b], 1.f);
    }
}

__device__ __forceinline__ float selu_f(float x) {
    const float alpha = 1.6732632423543772f;
    const float scale = 1.0507009873554805f;
    return x > 0.f ? scale * x : scale * alpha * expm1f(x);
}

__global__ void mlp_kernel(const float* __restrict__ W1,
                           const float* __restrict__ b1,
                           const float* __restrict__ W2,
                           const float* __restrict__ b2,
                           const float* __restrict__ W3,
                           const float* __restrict__ b3,
                           const float* __restrict__ W4,
                           const float* __restrict__ b4,
                           float* __restrict__ out) {
    __shared__ float sbuf[32][280];
    int warp = threadIdx.x >> 5, lane = threadIdx.x & 31;
    int b = blockIdx.x * 32 + warp;
    if (b >= BATCH) return;
    float* buf = sbuf[warp];

    float cnt = fmaxf(g_counts[b], 1.f);
    buf[lane] = g_pooled[b * 32 + lane] / cnt;
    __syncwarp();

#pragma unroll
    for (int r = 0; r < 4; r++) {
        int o = lane + 32 * r;
        float a = b1[o];
        for (int k = 0; k < 32; k++) a = fmaf(buf[k], W1[k * 128 + o], a);
        buf[32 + o] = selu_f(a);
    }
    __syncwarp();
#pragma unroll
    for (int r = 0; r < 2; r++) {
        int o = lane + 32 * r;
        float a = b2[o];
        for (int k = 0; k < 128; k++) a = fmaf(buf[32 + k], W2[k * 64 + o], a);
        buf[160 + o] = selu_f(a);
    }
    __syncwarp();
    {
        int o = lane;
        float a = b3[o];
        for (int k = 0; k < 64; k++) a = fmaf(buf[160 + k], W3[k * 32 + o], a);
        buf[224 + o] = selu_f(a);
    }
    __syncwarp();
    if (lane < 21) {
        float a = b4[lane];
        for (int k = 0; k < 32; k++) a = fmaf(buf[224 + k], W4[k * 21 + lane], a);
        buf[256 + lane] = a;
    }
    __syncwarp();
    for (int r = lane; r < 36; r += 32) out[b * 36 + r] = buf[256 + c_IDX[r]];
}

// ---------------------------------------------------------------------------
extern "C" void kernel_launch(void* const* d_in, const int* in_sizes, int n_in,
                              void* d_out, int out_size) {
    const float* node_attrs = (const float*)d_in[0];
    const float* positions = (const float*)d_in[1];
    const float* shifts = (const float*)d_in[2];
    const float* edge_attr = (const float*)d_in[3];
    const int* edge_index = (const int*)d_in[4];
    const int* batch_ids = (const int*)d_in[5];
    const float* embed_W = (const float*)d_in[6];
    const float* embed_b = (const float*)d_in[7];
    const float* e_W1 = (const float*)d_in[8];
    const float* e_b1 = (const float*)d_in[9];
    const float* e_W2 = (const float*)d_in[10];
    const float* e_b2 = (const float*)d_in[11];
    const float* e_W3 = (const float*)d_in[12];
    const float* e_b3 = (const float*)d_in[13];
    const float* conv_b = (const float*)d_in[14];
    const float* h_W1 = (const float*)d_in[15];
    const float* h_b1 = (const float*)d_in[16];
    const float* h_W2 = (const float*)d_in[17];
    const float* h_b2 = (const float*)d_in[18];
    const float* h_W3 = (const float*)d_in[19];
    const float* h_b3 = (const float*)d_in[20];
    const float* h_W4 = (const float*)d_in[21];
    const float* h_b4 = (const float*)d_in[22];

    int N = in_sizes[0];
    int E = in_sizes[3];
    if (N > NMAX) N = NMAX;
    if (E > EMAX) E = EMAX;

    cudaFuncSetAttribute(edge_kernel,
                         cudaFuncAttributeMaxDynamicSharedMemorySize,
                         SMEM_TOTAL);

    int tot = N * 32;
    int blk = 256;
    init_kernel<<<(tot + blk - 1) / blk, blk>>>(node_attrs, embed_W, embed_b, N);

    for (int l = 0; l < 3; l++) {
        edge_kernel<<<148, NTHREADS, SMEM_TOTAL>>>(
            positions, shifts, edge_attr, edge_index, e_W1 + l * 160,
            e_b1 + l * 32, e_W2 + l * 1024, e_b2 + l * 32, e_W3 + l * 32768,
            e_b3 + l * 1024, E);
        node_kernel<<<(tot + blk - 1) / blk, blk>>>(conv_b + l * 32, N);
    }

    pool_kernel<<<(tot + blk - 1) / blk, blk>>>(batch_ids, N);
    mlp_kernel<<<2, 1024>>>(h_W1, h_b1, h_W2, h_b2, h_W3, h_b3, h_W4, h_b4,
                            (float*)d_out);
}